// round 5
// baseline (speedup 1.0000x reference)
#include <cuda_runtime.h>
#include <cuda_bf16.h>
#include <cstdint>
#include <math.h>

// Problem constants
#define Bc   32
#define Nn   4096
#define FDc  256
#define Dc   256
#define Hc   4
#define NFc  8
#define DHc  64
#define SCALEF 0.125f     // DH^-0.5
#define EPSF   1e-8f
#define LNEPS  1e-5f

// -------- scratch (device globals: allocation-free) --------
__device__ float g_stats[2 * 131072];          // per-row mean,rstd of inputs
__device__ float g_K[33554432];                // [B,N,256]
__device__ float g_V[33554432];                // [B,N,256]
__device__ float g_attn[32 * 32 * 4096];       // [b][ih][j] raw softmax
__device__ float g_rowsum[1024];               // [b][ih]
__device__ float g_fill[65536];                // fillers [b,slot,256]
__device__ float g_f[65536];                   // LN(fillers)
__device__ float g_q[65536];                   // q
__device__ float g_upd[65536];                 // updates
__device__ float g_gates[2 * 256 * 768];       // [gi|gh][row][768]

// ---------------- helpers ----------------
__device__ __forceinline__ unsigned smem_u32(const void* p) {
    return (unsigned)__cvta_generic_to_shared(p);
}
__device__ __forceinline__ void ldm4(unsigned* r, unsigned a) {
    asm volatile("ldmatrix.sync.aligned.m8n8.x4.shared.b16 {%0,%1,%2,%3},[%4];\n"
                 : "=r"(r[0]), "=r"(r[1]), "=r"(r[2]), "=r"(r[3]) : "r"(a));
}
__device__ __forceinline__ void mma_bf16(float* c, const unsigned* a, const unsigned* b) {
    asm volatile(
        "mma.sync.aligned.m16n8k16.row.col.f32.bf16.bf16.f32 "
        "{%0,%1,%2,%3},{%4,%5,%6,%7},{%8,%9},{%0,%1,%2,%3};\n"
        : "+f"(c[0]), "+f"(c[1]), "+f"(c[2]), "+f"(c[3])
        : "r"(a[0]), "r"(a[1]), "r"(a[2]), "r"(a[3]), "r"(b[0]), "r"(b[1]));
}
__device__ __forceinline__ unsigned packh(__nv_bfloat16 a, __nv_bfloat16 b) {
    unsigned short lo = __bfloat16_as_ushort(a);
    unsigned short hi = __bfloat16_as_ushort(b);
    return (unsigned)lo | ((unsigned)hi << 16);
}

// ---------------- row stats of inputs (mean, rstd over FD=256) ----------------
__global__ void k_rowstats(const float* __restrict__ x) {
    int warp = (blockIdx.x * blockDim.x + threadIdx.x) >> 5;   // row id
    int lane = threadIdx.x & 31;
    const float* r = x + (size_t)warp * 256;
    float v[8];
    float s = 0.f;
#pragma unroll
    for (int u = 0; u < 8; u++) { v[u] = r[lane + 32 * u]; s += v[u]; }
#pragma unroll
    for (int o = 16; o > 0; o >>= 1) s += __shfl_xor_sync(0xffffffffu, s, o);
    float m = s * (1.f / 256.f);
    float ss = 0.f;
#pragma unroll
    for (int u = 0; u < 8; u++) { float d = v[u] - m; ss += d * d; }
#pragma unroll
    for (int o = 16; o > 0; o >>= 1) ss += __shfl_xor_sync(0xffffffffu, ss, o);
    if (lane == 0) {
        g_stats[2 * warp + 0] = m;
        g_stats[2 * warp + 1] = rsqrtf(ss * (1.f / 256.f) + LNEPS);
    }
}

// ---------------- big GEMM on tensor cores (bf16 3x-split, fp32 accum) -------
// K = LN(x) @ Wk^T, V = LN(x) @ Wv^T.
// grid (4, 1024): blockIdx.x = {ntile, kv} (fast -> L2 reuse of A rows),
// blockIdx.y = m-tile. 512 threads, 16 warps (4x4), warp tile 32x32.
// Double-buffered smem (48KB exactly) + register prefetch of next k-chunk.
__global__ void __launch_bounds__(512)
k_kv_gemm(const float* __restrict__ x,
          const float* __restrict__ Wk, const float* __restrict__ Wv,
          const float* __restrict__ lg, const float* __restrict__ lb) {
    __shared__ __nv_bfloat16 Ah[2][128][24], Al[2][128][24];
    __shared__ __nv_bfloat16 Bh[2][128][24], Bl[2][128][24];

    int t = threadIdx.x;
    int ntile = blockIdx.x & 1, kv = blockIdx.x >> 1;
    int row0 = blockIdx.y * 128;
    int col0 = ntile * 128;
    const float* W = kv ? Wv : Wk;
    float* out     = kv ? g_V : g_K;

    int wid = t >> 5, lane = t & 31;
    int wm0 = (wid >> 2) * 32;    // warp row base
    int wn0 = (wid & 3) * 32;     // warp col base

    // global load mapping: 4 threads per row, 4 floats (one float4) each
    int lrow = t >> 2;            // 0..127
    int kq   = (t & 3) * 4;       // 0,4,8,12 within 16-k chunk
    float mean = g_stats[2 * (row0 + lrow) + 0];
    float rstd = g_stats[2 * (row0 + lrow) + 1];
    const float* arow = x + (size_t)(row0 + lrow) * 256;
    const float* brow = W + (size_t)(col0 + lrow) * 256;

    // ldmatrix lane addressing
    int lr = (lane & 7) + ((lane >> 3) & 1) * 8;
    int lk = (lane >> 4) * 8;
    unsigned aAh[2], aAl[2], aBh[2], aBl[2];
#pragma unroll
    for (int mt = 0; mt < 2; mt++) {
        aAh[mt] = smem_u32(&Ah[0][wm0 + mt * 16 + lr][lk]);
        aAl[mt] = smem_u32(&Al[0][wm0 + mt * 16 + lr][lk]);
    }
#pragma unroll
    for (int g2 = 0; g2 < 2; g2++) {
        aBh[g2] = smem_u32(&Bh[0][wn0 + g2 * 16 + lr][lk]);
        aBl[g2] = smem_u32(&Bl[0][wn0 + g2 * 16 + lr][lk]);
    }

    float acc[2][4][4];
#pragma unroll
    for (int i = 0; i < 2; i++)
#pragma unroll
        for (int j = 0; j < 4; j++)
#pragma unroll
            for (int r = 0; r < 4; r++) acc[i][j][r] = 0.f;

    // prefetch k-chunk 0
    float4 va = *(const float4*)(arow + kq);
    float4 vb = *(const float4*)(brow + kq);

    for (int k0 = 0; k0 < 256; k0 += 16) {
        int s = (k0 >> 4) & 1;
        unsigned soff = (unsigned)s * (128 * 24 * 2);   // stage byte offset

        // ---- convert & store current chunk
        {
            float g0 = __ldg(lg + k0 + kq + 0), g1 = __ldg(lg + k0 + kq + 1);
            float g2v = __ldg(lg + k0 + kq + 2), g3 = __ldg(lg + k0 + kq + 3);
            float b0 = __ldg(lb + k0 + kq + 0), b1 = __ldg(lb + k0 + kq + 1);
            float b2 = __ldg(lb + k0 + kq + 2), b3 = __ldg(lb + k0 + kq + 3);
            float a0 = (va.x - mean) * rstd * g0 + b0;
            float a1 = (va.y - mean) * rstd * g1 + b1;
            float a2 = (va.z - mean) * rstd * g2v + b2;
            float a3 = (va.w - mean) * rstd * g3 + b3;
            __nv_bfloat16 h0 = __float2bfloat16(a0), h1 = __float2bfloat16(a1);
            __nv_bfloat16 h2 = __float2bfloat16(a2), h3 = __float2bfloat16(a3);
            *(uint2*)&Ah[s][lrow][kq] = make_uint2(packh(h0, h1), packh(h2, h3));
            *(uint2*)&Al[s][lrow][kq] = make_uint2(
                packh(__float2bfloat16(a0 - __bfloat162float(h0)),
                      __float2bfloat16(a1 - __bfloat162float(h1))),
                packh(__float2bfloat16(a2 - __bfloat162float(h2)),
                      __float2bfloat16(a3 - __bfloat162float(h3))));
            __nv_bfloat16 w0 = __float2bfloat16(vb.x), w1 = __float2bfloat16(vb.y);
            __nv_bfloat16 w2 = __float2bfloat16(vb.z), w3 = __float2bfloat16(vb.w);
            *(uint2*)&Bh[s][lrow][kq] = make_uint2(packh(w0, w1), packh(w2, w3));
            *(uint2*)&Bl[s][lrow][kq] = make_uint2(
                packh(__float2bfloat16(vb.x - __bfloat162float(w0)),
                      __float2bfloat16(vb.y - __bfloat162float(w1))),
                packh(__float2bfloat16(vb.z - __bfloat162float(w2)),
                      __float2bfloat16(vb.w - __bfloat162float(w3))));
        }
        __syncthreads();

        // ---- prefetch next chunk (hidden under ldmatrix + MMA)
        if (k0 + 16 < 256) {
            va = *(const float4*)(arow + k0 + 16 + kq);
            vb = *(const float4*)(brow + k0 + 16 + kq);
        }

        // ---- fragments
        unsigned afh[2][4], afl[2][4], bfh[2][4], bfl[2][4];
#pragma unroll
        for (int mt = 0; mt < 2; mt++) {
            ldm4(afh[mt], aAh[mt] + soff);
            ldm4(afl[mt], aAl[mt] + soff);
        }
#pragma unroll
        for (int g2 = 0; g2 < 2; g2++) {
            ldm4(bfh[g2], aBh[g2] + soff);
            ldm4(bfl[g2], aBl[g2] + soff);
        }

#pragma unroll
        for (int mt = 0; mt < 2; mt++)
#pragma unroll
            for (int nt = 0; nt < 4; nt++) {
                int g2 = nt >> 1, hf = nt & 1;
                unsigned bh[2] = {bfh[g2][hf], bfh[g2][hf + 2]};
                unsigned bl[2] = {bfl[g2][hf], bfl[g2][hf + 2]};
                mma_bf16(acc[mt][nt], afh[mt], bh);
                mma_bf16(acc[mt][nt], afh[mt], bl);
                mma_bf16(acc[mt][nt], afl[mt], bh);
            }
    }

    int cr = lane >> 2, cc = 2 * (lane & 3);
#pragma unroll
    for (int mt = 0; mt < 2; mt++)
#pragma unroll
        for (int nt = 0; nt < 4; nt++) {
            int r = row0 + wm0 + mt * 16 + cr;
            int c = col0 + wn0 + nt * 8 + cc;
            float2 v0 = {acc[mt][nt][0], acc[mt][nt][1]};
            float2 v1 = {acc[mt][nt][2], acc[mt][nt][3]};
            *(float2*)&out[(size_t)r * 256 + c]       = v0;
            *(float2*)&out[(size_t)(r + 8) * 256 + c] = v1;
        }
}

// ---------------- small GEMM: C[256 x Ncols] = A[256,256] @ W[Ncols,256]^T + bias
__global__ void __launch_bounds__(256)
k_gemm64(int mode, const float* __restrict__ W, const float* __restrict__ bias) {
    const float* A;
    float* C;
    int ldc;
    if (mode == 0)      { A = g_f;    C = g_q;              ldc = 256; }
    else if (mode == 1) { A = g_upd;  C = g_gates;          ldc = 768; }
    else                { A = g_fill; C = g_gates + 196608; ldc = 768; }

    __shared__ float As[64][17];
    __shared__ float Bs[64][17];
    int t = threadIdx.x;
    int row0 = blockIdx.x * 64, col0 = blockIdx.y * 64;
    int tx = t & 15, ty = t >> 4;

    float acc[4][4];
#pragma unroll
    for (int i = 0; i < 4; i++)
#pragma unroll
        for (int j = 0; j < 4; j++) acc[i][j] = 0.f;

    for (int k0 = 0; k0 < 256; k0 += 16) {
        __syncthreads();
        {
            int row = t >> 2, kp = t & 3;
            float4 a4 = *(const float4*)(A + (size_t)(row0 + row) * 256 + k0 + kp * 4);
            As[row][kp * 4 + 0] = a4.x;
            As[row][kp * 4 + 1] = a4.y;
            As[row][kp * 4 + 2] = a4.z;
            As[row][kp * 4 + 3] = a4.w;
            float4 b4 = *(const float4*)(W + (size_t)(col0 + row) * 256 + k0 + kp * 4);
            Bs[row][kp * 4 + 0] = b4.x;
            Bs[row][kp * 4 + 1] = b4.y;
            Bs[row][kp * 4 + 2] = b4.z;
            Bs[row][kp * 4 + 3] = b4.w;
        }
        __syncthreads();
#pragma unroll
        for (int kk = 0; kk < 16; kk++) {
            float a[4], bb[4];
#pragma unroll
            for (int i = 0; i < 4; i++) a[i]  = As[ty + 16 * i][kk];
#pragma unroll
            for (int j = 0; j < 4; j++) bb[j] = Bs[tx + 16 * j][kk];
#pragma unroll
            for (int i = 0; i < 4; i++)
#pragma unroll
                for (int j = 0; j < 4; j++) acc[i][j] += a[i] * bb[j];
        }
    }
#pragma unroll
    for (int i = 0; i < 4; i++)
#pragma unroll
        for (int j = 0; j < 4; j++) {
            float c = acc[i][j];
            if (bias) c += bias[col0 + tx + 16 * j];
            C[(size_t)(row0 + ty + 16 * i) * ldc + col0 + tx + 16 * j] = c;
        }
}

// ---------------- LN(fillers) + zero rowsum + zero g_upd ----------------
__global__ void k_lnfill(const float* __restrict__ g, const float* __restrict__ b) {
    int t = threadIdx.x;
    int gt = blockIdx.x * 256 + t;         // 8192 threads total
#pragma unroll
    for (int u = 0; u < 8; u++) g_upd[gt + 8192 * u] = 0.f;
    if (gt < 1024) g_rowsum[gt] = 0.f;

    int row  = blockIdx.x * 8 + (t >> 5);  // 256 rows total
    int lane = t & 31;
    const float* r = g_fill + row * 256;
    float v[8];
    float s = 0.f;
#pragma unroll
    for (int u = 0; u < 8; u++) { v[u] = r[lane + 32 * u]; s += v[u]; }
#pragma unroll
    for (int o = 16; o > 0; o >>= 1) s += __shfl_xor_sync(0xffffffffu, s, o);
    float m = s * (1.f / 256.f);
    float ss = 0.f;
#pragma unroll
    for (int u = 0; u < 8; u++) { float d = v[u] - m; ss += d * d; }
#pragma unroll
    for (int o = 16; o > 0; o >>= 1) ss += __shfl_xor_sync(0xffffffffu, ss, o);
    float rstd = rsqrtf(ss * (1.f / 256.f) + LNEPS);
#pragma unroll
    for (int u = 0; u < 8; u++) {
        int c = lane + 32 * u;
        g_f[row * 256 + c] = (v[u] - m) * rstd * g[c] + b[c];
    }
}

// ---------------- dots + inverted softmax (over 32 (slot,head) per (b,j)) ----------------
__global__ void __launch_bounds__(256)
k_dots(int last, float* __restrict__ attn_out) {
    int b = blockIdx.x;
    int w = threadIdx.x >> 5, lane = threadIdx.x & 31;
    int j0 = blockIdx.y * 256 + w * 32;

    __shared__ float buf[8][32][33];

    int i = lane >> 2, h = lane & 3;
    const float4* q4 = (const float4*)(g_q + b * 2048 + i * 256 + h * 64);
    float4 qr[16];
#pragma unroll
    for (int p = 0; p < 16; p++) {
        float4 q = q4[p];
        q.x *= SCALEF; q.y *= SCALEF; q.z *= SCALEF; q.w *= SCALEF;
        qr[p] = q;
    }

    float rs = 0.f;
    for (int jj = 0; jj < 32; jj++) {
        int j = j0 + jj;
        const float4* k4 = (const float4*)(g_K + (size_t)(b * 4096 + j) * 256 + h * 64);
        float dot = 0.f;
#pragma unroll
        for (int p = 0; p < 16; p++) {
            float4 kv = k4[p];
            dot += qr[p].x * kv.x + qr[p].y * kv.y + qr[p].z * kv.z + qr[p].w * kv.w;
        }
        float mx = dot;
#pragma unroll
        for (int o = 16; o > 0; o >>= 1) mx = fmaxf(mx, __shfl_xor_sync(0xffffffffu, mx, o));
        float e = expf(dot - mx);
        float sm = e;
#pragma unroll
        for (int o = 16; o > 0; o >>= 1) sm += __shfl_xor_sync(0xffffffffu, sm, o);
        float at = e / sm;
        buf[w][lane][jj] = at;
        rs += at;
    }
    atomicAdd(&g_rowsum[b * 32 + lane], rs);
    __syncwarp();

#pragma unroll 4
    for (int r = 0; r < 32; r++)
        g_attn[((size_t)b * 32 + r) * 4096 + j0 + lane] = buf[w][r][lane];

    if (last) {
#pragma unroll
        for (int ii = 0; ii < 8; ii++) {
            float v = 0.25f * (buf[w][4 * ii + 0][lane] + buf[w][4 * ii + 1][lane] +
                               buf[w][4 * ii + 2][lane] + buf[w][4 * ii + 3][lane]);
            attn_out[((size_t)b * 8 + ii) * 4096 + j0 + lane] = v;
        }
    }
}

// ---------------- updates = einsum('bjhd,bihj->bihd', V, a) ----------------
__global__ void __launch_bounds__(256)
k_updates() {
    int b = blockIdx.x, h = blockIdx.y, jc = blockIdx.z;
    int t = threadIdx.x;
    int d = t & 63, ig = t >> 6;
    int i0 = 2 * ig, i1 = i0 + 1;

    __shared__ float a_s[8][64];
    __shared__ float inv_s[8];
    if (t < 8) inv_s[t] = 1.f / (g_rowsum[b * 32 + t * 4 + h] + 4096.f * EPSF);

    float acc0 = 0.f, acc1 = 0.f;
    int jbase = jc * 512;
    for (int jt = 0; jt < 512; jt += 64) {
        __syncthreads();
#pragma unroll
        for (int s = 0; s < 2; s++) {
            int e = t + 256 * s;
            int ri = e >> 6, jj = e & 63;
            a_s[ri][jj] = (g_attn[((size_t)b * 32 + ri * 4 + h) * 4096 + jbase + jt + jj] + EPSF) * inv_s[ri];
        }
        __syncthreads();
        const float* vp = g_V + (size_t)(b * 4096 + jbase + jt) * 256 + h * 64 + d;
#pragma unroll 4
        for (int jj = 0; jj < 64; jj++) {
            float vv = vp[jj * 256];
            acc0 += vv * a_s[i0][jj];
            acc1 += vv * a_s[i1][jj];
        }
    }
    atomicAdd(&g_upd[b * 2048 + i0 * 256 + h * 64 + d], acc0);
    atomicAdd(&g_upd[b * 2048 + i1 * 256 + h * 64 + d], acc1);
}

// ---------------- GRU elementwise ----------------
__global__ void k_gru() {
    int idx = blockIdx.x * blockDim.x + threadIdx.x;   // 65536
    int r = idx >> 8, c = idx & 255;
    const float* gi = g_gates + (size_t)r * 768;
    const float* gh = g_gates + 196608 + (size_t)r * 768;
    float ir = gi[c], iz = gi[c + 256], in = gi[c + 512];
    float hr = gh[c], hz = gh[c + 256], hn = gh[c + 512];
    float rr = 1.f / (1.f + expf(-(ir + hr)));
    float zz = 1.f / (1.f + expf(-(iz + hz)));
    float nn = tanhf(in + rr * hn);
    float hp = g_fill[idx];
    g_fill[idx] = (1.f - zz) * nn + zz * hp;
}

// ---------------- copies ----------------
__global__ void k_copyin(const float* __restrict__ src) {
    int idx = blockIdx.x * blockDim.x + threadIdx.x;
    g_fill[idx] = src[idx];
}
__global__ void k_copyout(float* __restrict__ dst) {
    int idx = blockIdx.x * blockDim.x + threadIdx.x;
    dst[idx] = g_fill[idx];
}

// ---------------- launcher ----------------
extern "C" void kernel_launch(void* const* d_in, const int* in_sizes, int n_in,
                              void* d_out, int out_size) {
    const float* inputs = (const float*)d_in[0];
    const float* cond   = (const float*)d_in[1];
    const float* Wq     = (const float*)d_in[2];
    const float* Wk     = (const float*)d_in[3];
    const float* Wv     = (const float*)d_in[4];
    const float* W_ih   = (const float*)d_in[5];
    const float* W_hh   = (const float*)d_in[6];
    const float* b_ih   = (const float*)d_in[7];
    const float* b_hh   = (const float*)d_in[8];
    const float* lig    = (const float*)d_in[9];
    const float* lib    = (const float*)d_in[10];
    const float* lfg    = (const float*)d_in[11];
    const float* lfb    = (const float*)d_in[12];
    float* out = (float*)d_out;

    k_rowstats<<<16384, 256>>>(inputs);
    k_kv_gemm<<<dim3(4, 1024), 512>>>(inputs, Wk, Wv, lig, lib);
    k_copyin<<<64, 1024>>>(cond);

    for (int it = 0; it < 3; it++) {
        k_lnfill<<<32, 256>>>(lfg, lfb);
        k_gemm64<<<dim3(4, 4), 256>>>(0, Wq, (const float*)0);
        k_dots<<<dim3(32, 16), 256>>>(it == 2 ? 1 : 0, out + 65536);
        k_updates<<<dim3(32, 4, 8), 256>>>();
        k_gemm64<<<dim3(4, 12), 256>>>(1, W_ih, b_ih);
        k_gemm64<<<dim3(4, 12), 256>>>(2, W_hh, b_hh);
        k_gru<<<256, 256>>>();
    }
    k_copyout<<<64, 1024>>>(out);
}

// round 8
// speedup vs baseline: 1.6161x; 1.6161x over previous
#include <cuda_runtime.h>
#include <cstdint>
#include <math.h>

#define SCALEF 0.125f     // DH^-0.5
#define EPSF   1e-8f
#define LNEPS  1e-5f

// -------- scratch (device globals: allocation-free) --------
__device__ float g_stats[2 * 131072];     // per-row mean,rstd of inputs
__device__ float g_lnx[33554432];         // LN(inputs) [b][j][256]
__device__ float g_P[4 * 256 * 256];      // P_h[e][c] = sum_d Wq[h64+d][e] Wk[h64+d][c]
__device__ float g_t[1024 * 256];         // t [(b,ih)][c]  (SCALE folded in)
__device__ float g_attn[32 * 32 * 4096];  // [b][ih][j] raw softmax
__device__ float g_rowsum[1024];          // [b][ih]
__device__ float g_fill[65536];           // fillers [b,slot,256]
__device__ float g_f[65536];              // LN(fillers)
__device__ float g_s[1024 * 256];         // s [(b,ih)][c]
__device__ float g_upd[65536];            // updates [b*8+i][256]
__device__ float g_gates[2 * 256 * 768];  // [gi|gh][row][768]

// ---------------- packed f32x2 helpers ----------------
__device__ __forceinline__ unsigned long long ffma2(unsigned long long a,
                                                    unsigned long long b,
                                                    unsigned long long c) {
    unsigned long long d;
    asm("fma.rn.f32x2 %0, %1, %2, %3;" : "=l"(d) : "l"(a), "l"(b), "l"(c));
    return d;
}
__device__ __forceinline__ unsigned long long bcast2(float x) {
    unsigned u = __float_as_uint(x);
    return ((unsigned long long)u << 32) | (unsigned long long)u;
}
__device__ __forceinline__ float lo2(unsigned long long v) { return __uint_as_float((unsigned)v); }
__device__ __forceinline__ float hi2(unsigned long long v) { return __uint_as_float((unsigned)(v >> 32)); }

// ---------------- row stats of inputs ----------------
__global__ void k_rowstats(const float* __restrict__ x) {
    int warp = (blockIdx.x * blockDim.x + threadIdx.x) >> 5;
    int lane = threadIdx.x & 31;
    const float* r = x + (size_t)warp * 256;
    float v[8];
    float s = 0.f;
#pragma unroll
    for (int u = 0; u < 8; u++) { v[u] = r[lane + 32 * u]; s += v[u]; }
#pragma unroll
    for (int o = 16; o > 0; o >>= 1) s += __shfl_xor_sync(0xffffffffu, s, o);
    float m = s * (1.f / 256.f);
    float ss = 0.f;
#pragma unroll
    for (int u = 0; u < 8; u++) { float d = v[u] - m; ss += d * d; }
#pragma unroll
    for (int o = 16; o > 0; o >>= 1) ss += __shfl_xor_sync(0xffffffffu, ss, o);
    if (lane == 0) {
        g_stats[2 * warp + 0] = m;
        g_stats[2 * warp + 1] = rsqrtf(ss * (1.f / 256.f) + LNEPS);
    }
}

// ---------------- materialize LN(inputs) ----------------
__global__ void k_lnx(const float* __restrict__ x, const float* __restrict__ g,
                      const float* __restrict__ b) {
    int gi = blockIdx.x * 256 + threadIdx.x;   // float4 index
    int row = gi >> 6;
    int c4 = (gi & 63) * 4;
    float m = g_stats[2 * row + 0], r = g_stats[2 * row + 1];
    float4 v = *(const float4*)(x + (size_t)gi * 4);
    float4 o;
    o.x = (v.x - m) * r * g[c4 + 0] + b[c4 + 0];
    o.y = (v.y - m) * r * g[c4 + 1] + b[c4 + 1];
    o.z = (v.z - m) * r * g[c4 + 2] + b[c4 + 2];
    o.w = (v.w - m) * r * g[c4 + 3] + b[c4 + 3];
    *(float4*)(g_lnx + (size_t)gi * 4) = o;
}

// ---------------- P_h = Wq_h^T @ Wk_h (once) ----------------
__global__ void __launch_bounds__(256)
k_pcomp(const float* __restrict__ Wq, const float* __restrict__ Wk) {
    int h = blockIdx.x, et = blockIdx.y, ct = blockIdx.z;
    int e0 = et * 64, c0 = ct * 64;
    int t = threadIdx.x;
    int tx = t & 15, ty = t >> 4;

    __shared__ float Qs[64][65];
    __shared__ float Ks[64][65];
    int d = t >> 2, sg = (t & 3) * 16;
#pragma unroll
    for (int q = 0; q < 4; q++) {
        float4 vq = *(const float4*)(Wq + (size_t)(h * 64 + d) * 256 + e0 + sg + q * 4);
        Qs[d][sg + q * 4 + 0] = vq.x; Qs[d][sg + q * 4 + 1] = vq.y;
        Qs[d][sg + q * 4 + 2] = vq.z; Qs[d][sg + q * 4 + 3] = vq.w;
        float4 vk = *(const float4*)(Wk + (size_t)(h * 64 + d) * 256 + c0 + sg + q * 4);
        Ks[d][sg + q * 4 + 0] = vk.x; Ks[d][sg + q * 4 + 1] = vk.y;
        Ks[d][sg + q * 4 + 2] = vk.z; Ks[d][sg + q * 4 + 3] = vk.w;
    }
    __syncthreads();
    float acc[4][4];
#pragma unroll
    for (int i = 0; i < 4; i++)
#pragma unroll
        for (int j = 0; j < 4; j++) acc[i][j] = 0.f;
    for (int dd = 0; dd < 64; dd++) {
        float a[4], bb[4];
#pragma unroll
        for (int i = 0; i < 4; i++) a[i] = Qs[dd][ty + 16 * i];
#pragma unroll
        for (int j = 0; j < 4; j++) bb[j] = Ks[dd][tx + 16 * j];
#pragma unroll
        for (int i = 0; i < 4; i++)
#pragma unroll
            for (int j = 0; j < 4; j++) acc[i][j] += a[i] * bb[j];
    }
#pragma unroll
    for (int i = 0; i < 4; i++)
#pragma unroll
        for (int j = 0; j < 4; j++)
            g_P[(size_t)h * 65536 + (size_t)(e0 + ty + 16 * i) * 256 + c0 + tx + 16 * j] = acc[i][j];
}

// ---------------- LN(fillers) + zero s/rowsum (+copy cond on iter0) ----------
__global__ void k_lnfill(const float* __restrict__ g, const float* __restrict__ b,
                         const float* __restrict__ cond, int first) {
    int t = threadIdx.x;
    int gt = blockIdx.x * 256 + t;   // 8192 threads total
#pragma unroll
    for (int u = 0; u < 32; u++) g_s[gt + 8192 * u] = 0.f;
    if (gt < 1024) g_rowsum[gt] = 0.f;

    int row  = blockIdx.x * 8 + (t >> 5);   // 256 rows
    int lane = t & 31;
    const float* r = (first ? cond : g_fill) + (size_t)row * 256;
    float v[8];
    float s = 0.f;
#pragma unroll
    for (int u = 0; u < 8; u++) { v[u] = r[lane + 32 * u]; s += v[u]; }
#pragma unroll
    for (int o = 16; o > 0; o >>= 1) s += __shfl_xor_sync(0xffffffffu, s, o);
    float m = s * (1.f / 256.f);
    float ss = 0.f;
#pragma unroll
    for (int u = 0; u < 8; u++) { float d = v[u] - m; ss += d * d; }
#pragma unroll
    for (int o = 16; o > 0; o >>= 1) ss += __shfl_xor_sync(0xffffffffu, ss, o);
    float rstd = rsqrtf(ss * (1.f / 256.f) + LNEPS);
#pragma unroll
    for (int u = 0; u < 8; u++) {
        int c = lane + 32 * u;
        if (first) g_fill[row * 256 + c] = v[u];
        g_f[row * 256 + c] = (v[u] - m) * rstd * g[c] + b[c];
    }
}

// ---------------- t = SCALE * f @ P_h  ([32 ih x 64 c] per (b,ct)) ------------
__global__ void __launch_bounds__(256)
k_tgemm() {
    int b = blockIdx.x, ct = blockIdx.y;
    int c0 = ct * 64;
    int t = threadIdx.x;
    int ihx = t >> 3, c8 = (t & 7) * 8;
    int h = ihx & 3, i = ihx >> 2;

    __shared__ float fs[2048];                       // f[b]: 8 slots x 256
    __shared__ __align__(16) float Ps[4][32][68];    // e-chunk of P per head

#pragma unroll
    for (int q = 0; q < 8; q++) fs[t + 256 * q] = g_f[b * 2048 + t + 256 * q];

    unsigned long long acc[4] = {0ull, 0ull, 0ull, 0ull};

    for (int ec = 0; ec < 8; ec++) {
        int e0 = ec * 32;
        __syncthreads();
#pragma unroll
        for (int q = 0; q < 8; q++) {
            int idx = t + 256 * q;               // float4 units, 0..2047
            int hh = idx >> 9, e = (idx >> 4) & 31, sg = idx & 15;
            float4 v = *(const float4*)(g_P + (size_t)hh * 65536 +
                                        (size_t)(e0 + e) * 256 + c0 + sg * 4);
            *(float4*)&Ps[hh][e][sg * 4] = v;
        }
        __syncthreads();
#pragma unroll
        for (int e = 0; e < 32; e++) {
            unsigned long long a = bcast2(fs[i * 256 + e0 + e]);
            ulonglong2 p0 = *(const ulonglong2*)&Ps[h][e][c8];
            ulonglong2 p1 = *(const ulonglong2*)&Ps[h][e][c8 + 4];
            acc[0] = ffma2(a, p0.x, acc[0]);
            acc[1] = ffma2(a, p0.y, acc[1]);
            acc[2] = ffma2(a, p1.x, acc[2]);
            acc[3] = ffma2(a, p1.y, acc[3]);
        }
    }
    int row = b * 32 + ihx;
#pragma unroll
    for (int q = 0; q < 4; q++) {
        g_t[(size_t)row * 256 + c0 + c8 + 2 * q]     = SCALEF * lo2(acc[q]);
        g_t[(size_t)row * 256 + c0 + c8 + 2 * q + 1] = SCALEF * hi2(acc[q]);
    }
}

// ---------------- dots = t @ LNx^T + inverted softmax ----------------
// grid (32 b, 32 jchunk of 128), 128 threads.
__global__ void __launch_bounds__(128)
k_dots(int last, float* __restrict__ attn_out) {
    int b = blockIdx.x, jc = blockIdx.y;
    int t = threadIdx.x;
    int tj = t & 15, tih = t >> 4;   // tj 0..15 (8 j each), tih 0..7 (4 ih each)
    int j0 = jc * 128;

    __shared__ __align__(16) unsigned long long t2[32][32];  // packed t per c-chunk
    __shared__ __align__(16) float Bs[32][132];              // LNx^T tile [c][j]
    __shared__ float dsm[32][129];                           // dots/attn [ih][j]

    unsigned long long acc[4][4];
#pragma unroll
    for (int ii = 0; ii < 4; ii++)
#pragma unroll
        for (int q = 0; q < 4; q++) acc[ii][q] = 0ull;

    const float* lnxb = g_lnx + (size_t)b * 4096 * 256;

    for (int cc = 0; cc < 8; cc++) {
        int c0 = cc * 32;
        __syncthreads();
#pragma unroll
        for (int q = 0; q < 8; q++) {
            int idx = t + 128 * q;               // 0..1023
            int ih = idx >> 5, c = idx & 31;
            t2[ih][c] = bcast2(g_t[(size_t)(b * 32 + ih) * 256 + c0 + c]);
        }
        {
            const float* src = lnxb + (size_t)(j0 + t) * 256 + c0;
#pragma unroll
            for (int q = 0; q < 8; q++) {
                float4 v = *(const float4*)(src + q * 4);
                Bs[q * 4 + 0][t] = v.x; Bs[q * 4 + 1][t] = v.y;
                Bs[q * 4 + 2][t] = v.z; Bs[q * 4 + 3][t] = v.w;
            }
        }
        __syncthreads();
#pragma unroll
        for (int c = 0; c < 32; c++) {
            ulonglong2 p0 = *(const ulonglong2*)&Bs[c][tj * 8];
            ulonglong2 p1 = *(const ulonglong2*)&Bs[c][tj * 8 + 4];
#pragma unroll
            for (int ii = 0; ii < 4; ii++) {
                unsigned long long a = t2[tih + 8 * ii][c];
                acc[ii][0] = ffma2(a, p0.x, acc[ii][0]);
                acc[ii][1] = ffma2(a, p0.y, acc[ii][1]);
                acc[ii][2] = ffma2(a, p1.x, acc[ii][2]);
                acc[ii][3] = ffma2(a, p1.y, acc[ii][3]);
            }
        }
    }
    __syncthreads();
#pragma unroll
    for (int ii = 0; ii < 4; ii++) {
        int ih = tih + 8 * ii;
#pragma unroll
        for (int q = 0; q < 4; q++) {
            dsm[ih][tj * 8 + 2 * q]     = lo2(acc[ii][q]);
            dsm[ih][tj * 8 + 2 * q + 1] = hi2(acc[ii][q]);
        }
    }
    __syncthreads();

    // softmax over 32 (slot,head) for column j = t
    float vcol[32];
    float mx = -1e30f;
#pragma unroll
    for (int ih = 0; ih < 32; ih++) { vcol[ih] = dsm[ih][t]; mx = fmaxf(mx, vcol[ih]); }
    float sum = 0.f;
#pragma unroll
    for (int ih = 0; ih < 32; ih++) { vcol[ih] = __expf(vcol[ih] - mx); sum += vcol[ih]; }
    float inv = 1.f / sum;
#pragma unroll
    for (int ih = 0; ih < 32; ih++) {
        float at = vcol[ih] * inv;
        vcol[ih] = at;
        g_attn[((size_t)b * 32 + ih) * 4096 + j0 + t] = at;
    }
    if (last) {
#pragma unroll
        for (int i = 0; i < 8; i++) {
            float v = 0.25f * (vcol[4 * i] + vcol[4 * i + 1] + vcol[4 * i + 2] + vcol[4 * i + 3]);
            attn_out[((size_t)b * 8 + i) * 4096 + j0 + t] = v;
        }
    }
    __syncthreads();
#pragma unroll
    for (int ih = 0; ih < 32; ih++) dsm[ih][t] = vcol[ih];
    __syncthreads();
    if (t < 32) {
        float s = 0.f;
#pragma unroll 4
        for (int j = 0; j < 128; j++) s += dsm[t][j];
        atomicAdd(&g_rowsum[b * 32 + t], s);
    }
}

// ---------------- s = anorm @ LNx  (K=512 j per block, atomic partials) -------
__global__ void __launch_bounds__(256)
k_sgemm() {
    int b = blockIdx.x, js = blockIdx.y;
    int t = threadIdx.x;
    int tc = t & 31, tih = t >> 5;
    int jbase = js * 512;

    __shared__ __align__(16) unsigned long long A2[32][16];
    __shared__ __align__(16) float Bs[16][260];
    __shared__ float inv_s[32];

    if (t < 32) inv_s[t] = 1.f / (g_rowsum[b * 32 + t] + 4096.f * EPSF);

    unsigned long long acc[4][4];
#pragma unroll
    for (int ii = 0; ii < 4; ii++)
#pragma unroll
        for (int q = 0; q < 4; q++) acc[ii][q] = 0ull;

    const float* lnxb = g_lnx + (size_t)b * 4096 * 256;

    for (int jt = 0; jt < 512; jt += 16) {
        __syncthreads();
#pragma unroll
        for (int q = 0; q < 4; q++) {
            int idx = t + 256 * q;               // float4 units 0..1023
            int j = idx >> 6, s4 = idx & 63;
            float4 v = *(const float4*)(lnxb + (size_t)(jbase + jt + j) * 256 + s4 * 4);
            *(float4*)&Bs[j][s4 * 4] = v;
        }
#pragma unroll
        for (int q = 0; q < 2; q++) {
            int idx = t + 256 * q;               // 0..511
            int ih = idx >> 4, j = idx & 15;
            float a = (g_attn[((size_t)b * 32 + ih) * 4096 + jbase + jt + j] + EPSF) * inv_s[ih];
            A2[ih][j] = bcast2(a);
        }
        __syncthreads();
#pragma unroll
        for (int j = 0; j < 16; j++) {
            ulonglong2 p0 = *(const ulonglong2*)&Bs[j][tc * 8];
            ulonglong2 p1 = *(const ulonglong2*)&Bs[j][tc * 8 + 4];
#pragma unroll
            for (int ii = 0; ii < 4; ii++) {
                unsigned long long a = A2[4 * tih + ii][j];
                acc[ii][0] = ffma2(a, p0.x, acc[ii][0]);
                acc[ii][1] = ffma2(a, p0.y, acc[ii][1]);
                acc[ii][2] = ffma2(a, p1.x, acc[ii][2]);
                acc[ii][3] = ffma2(a, p1.y, acc[ii][3]);
            }
        }
    }
#pragma unroll
    for (int ii = 0; ii < 4; ii++) {
        int row = b * 32 + 4 * tih + ii;
#pragma unroll
        for (int q = 0; q < 4; q++) {
            atomicAdd(&g_s[(size_t)row * 256 + tc * 8 + 2 * q],     lo2(acc[ii][q]));
            atomicAdd(&g_s[(size_t)row * 256 + tc * 8 + 2 * q + 1], hi2(acc[ii][q]));
        }
    }
}

// ---------------- upd = s @ Wv_h^T ----------------
__global__ void __launch_bounds__(256)
k_updproj(const float* __restrict__ Wv) {
    int b = blockIdx.x, dh2 = blockIdx.y;
    int t = threadIdx.x;
    int ihx = t >> 3, dq = (t & 7) * 4;
    int h = ihx & 3, i = ihx >> 2;
    int dbase = dh2 * 32;

    __shared__ __align__(16) float ss[32][256];
    __shared__ float Wvs[4][32][16];

#pragma unroll
    for (int q = 0; q < 8; q++) {
        int idx = t + 256 * q;               // float4 units 0..2047
        int ih = idx >> 6, s4 = idx & 63;
        *(float4*)&ss[ih][s4 * 4] = *(const float4*)(g_s + (size_t)(b * 32 + ih) * 256 + s4 * 4);
    }
    float acc[4] = {0.f, 0.f, 0.f, 0.f};

    for (int cc = 0; cc < 16; cc++) {
        int c0 = cc * 16;
        __syncthreads();
#pragma unroll
        for (int q = 0; q < 8; q++) {
            int idx = t + 256 * q;           // 0..2047
            int hh = idx >> 9, dd = (idx >> 4) & 31, c = idx & 15;
            Wvs[hh][dd][c] = Wv[(size_t)(hh * 64 + dbase + dd) * 256 + c0 + c];
        }
        __syncthreads();
#pragma unroll
        for (int c4 = 0; c4 < 4; c4++) {
            float4 sv = *(const float4*)&ss[ihx][c0 + c4 * 4];
#pragma unroll
            for (int k = 0; k < 4; k++) {
                const float* w = &Wvs[h][dq + k][c4 * 4];
                acc[k] += sv.x * w[0] + sv.y * w[1] + sv.z * w[2] + sv.w * w[3];
            }
        }
    }
#pragma unroll
    for (int k = 0; k < 4; k++)
        g_upd[(size_t)(b * 8 + i) * 256 + h * 64 + dbase + dq + k] = acc[k];
}

// ---------------- GRU gate GEMMs: C[256 x 768] = A @ W^T + bias --------------
__global__ void __launch_bounds__(256)
k_gemm64(int mode, const float* __restrict__ W, const float* __restrict__ bias) {
    const float* A = (mode == 1) ? g_upd : g_fill;
    float* C = (mode == 1) ? g_gates : (g_gates + 196608);

    __shared__ float As[64][17];
    __shared__ float Bs[64][17];
    int t = threadIdx.x;
    int row0 = blockIdx.x * 64, col0 = blockIdx.y * 64;
    int tx = t & 15, ty = t >> 4;

    float acc[4][4];
#pragma unroll
    for (int i = 0; i < 4; i++)
#pragma unroll
        for (int j = 0; j < 4; j++) acc[i][j] = 0.f;

    for (int k0 = 0; k0 < 256; k0 += 16) {
        __syncthreads();
        {
            int row = t >> 2, kp = t & 3;
            float4 a4 = *(const float4*)(A + (size_t)(row0 + row) * 256 + k0 + kp * 4);
            As[row][kp * 4 + 0] = a4.x; As[row][kp * 4 + 1] = a4.y;
            As[row][kp * 4 + 2] = a4.z; As[row][kp * 4 + 3] = a4.w;
            float4 b4 = *(const float4*)(W + (size_t)(col0 + row) * 256 + k0 + kp * 4);
            Bs[row][kp * 4 + 0] = b4.x; Bs[row][kp * 4 + 1] = b4.y;
            Bs[row][kp * 4 + 2] = b4.z; Bs[row][kp * 4 + 3] = b4.w;
        }
        __syncthreads();
#pragma unroll
        for (int kk = 0; kk < 16; kk++) {
            float a[4], bb[4];
#pragma unroll
            for (int i = 0; i < 4; i++) a[i]  = As[ty + 16 * i][kk];
#pragma unroll
            for (int j = 0; j < 4; j++) bb[j] = Bs[tx + 16 * j][kk];
#pragma unroll
            for (int i = 0; i < 4; i++)
#pragma unroll
                for (int j = 0; j < 4; j++) acc[i][j] += a[i] * bb[j];
        }
    }
#pragma unroll
    for (int i = 0; i < 4; i++)
#pragma unroll
        for (int j = 0; j < 4; j++)
            C[(size_t)(row0 + ty + 16 * i) * 768 + col0 + tx + 16 * j] =
                acc[i][j] + bias[col0 + tx + 16 * j];
}

// ---------------- GRU elementwise ----------------
__global__ void k_gru() {
    int idx = blockIdx.x * blockDim.x + threadIdx.x;   // 65536
    int r = idx >> 8, c = idx & 255;
    const float* gi = g_gates + (size_t)r * 768;
    const float* gh = g_gates + 196608 + (size_t)r * 768;
    float ir = gi[c], iz = gi[c + 256], in = gi[c + 512];
    float hr = gh[c], hz = gh[c + 256], hn = gh[c + 512];
    float rr = 1.f / (1.f + expf(-(ir + hr)));
    float zz = 1.f / (1.f + expf(-(iz + hz)));
    float nn = tanhf(in + rr * hn);
    float hp = g_fill[idx];
    g_fill[idx] = (1.f - zz) * nn + zz * hp;
}

__global__ void k_copyout(float* __restrict__ dst) {
    int idx = blockIdx.x * blockDim.x + threadIdx.x;
    dst[idx] = g_fill[idx];
}

// ---------------- launcher ----------------
extern "C" void kernel_launch(void* const* d_in, const int* in_sizes, int n_in,
                              void* d_out, int out_size) {
    const float* inputs = (const float*)d_in[0];
    const float* cond   = (const float*)d_in[1];
    const float* Wq     = (const float*)d_in[2];
    const float* Wk     = (const float*)d_in[3];
    const float* Wv     = (const float*)d_in[4];
    const float* W_ih   = (const float*)d_in[5];
    const float* W_hh   = (const float*)d_in[6];
    const float* b_ih   = (const float*)d_in[7];
    const float* b_hh   = (const float*)d_in[8];
    const float* lig    = (const float*)d_in[9];
    const float* lib    = (const float*)d_in[10];
    const float* lfg    = (const float*)d_in[11];
    const float* lfb    = (const float*)d_in[12];
    float* out = (float*)d_out;

    k_rowstats<<<16384, 256>>>(inputs);                       // launch 1
    k_lnx<<<32768, 256>>>(inputs, lig, lib);                  // launch 2
    k_pcomp<<<dim3(4, 4, 4), 256>>>(Wq, Wk);                  // launch 3

    for (int it = 0; it < 3; it++) {
        k_lnfill<<<32, 256>>>(lfg, lfb, cond, it == 0);       // 4
        k_tgemm<<<dim3(32, 4), 256>>>();                      // 5
        k_dots<<<dim3(32, 32), 128>>>(it == 2 ? 1 : 0, out + 65536);  // 6 (ncu -s 5)
        k_sgemm<<<dim3(32, 8), 256>>>();                      // 7
        k_updproj<<<dim3(32, 2), 256>>>(Wv);                  // 8
        k_gemm64<<<dim3(4, 12), 256>>>(1, W_ih, b_ih);        // 9
        k_gemm64<<<dim3(4, 12), 256>>>(2, W_hh, b_hh);        // 10
        k_gru<<<256, 256>>>();                                // 11
    }
    k_copyout<<<64, 1024>>>(out);
}

// round 9
// speedup vs baseline: 1.9625x; 1.2144x over previous
#include <cuda_runtime.h>
#include <cstdint>
#include <math.h>

#define SCALEF 0.125f     // DH^-0.5
#define EPSF   1e-8f
#define LNEPS  1e-5f

// -------- scratch (device globals: allocation-free) --------
__device__ float g_stats[2 * 131072];     // per-row mean,rstd of inputs
__device__ float g_lnx[33554432];         // LN(inputs) [b][j][256]
__device__ float g_L[8192];               // L[b][c] = sum_j lnx
__device__ float g_P[4 * 256 * 256];      // P_h = Wq_h^T Wk_h
__device__ float g_t[1024 * 256];         // t[(b,ih)][c] (SCALE folded)
__device__ float g_upart[16 * 1024 * 256];// u partials [js][(b,ih)][c]
__device__ float g_rowsum[1024];          // [b][ih]
__device__ float g_fill[65536];           // fillers
__device__ float g_f[65536];              // LN(fillers)
__device__ float g_upd[65536];            // updates
__device__ float g_gates[2 * 256 * 768];  // [gi|gh]

// ---------------- packed f32x2 helpers ----------------
__device__ __forceinline__ unsigned long long ffma2(unsigned long long a,
                                                    unsigned long long b,
                                                    unsigned long long c) {
    unsigned long long d;
    asm("fma.rn.f32x2 %0, %1, %2, %3;" : "=l"(d) : "l"(a), "l"(b), "l"(c));
    return d;
}
__device__ __forceinline__ unsigned long long bcast2(float x) {
    unsigned u = __float_as_uint(x);
    return ((unsigned long long)u << 32) | (unsigned long long)u;
}
__device__ __forceinline__ float lo2(unsigned long long v) { return __uint_as_float((unsigned)v); }
__device__ __forceinline__ float hi2(unsigned long long v) { return __uint_as_float((unsigned)(v >> 32)); }

// ---------------- row stats (also zero g_L) ----------------
__global__ void k_rowstats(const float* __restrict__ x) {
    int gid = blockIdx.x * blockDim.x + threadIdx.x;
    if (gid < 8192) g_L[gid] = 0.f;
    int warp = gid >> 5;
    int lane = threadIdx.x & 31;
    const float* r = x + (size_t)warp * 256;
    float v[8];
    float s = 0.f;
#pragma unroll
    for (int u = 0; u < 8; u++) { v[u] = r[lane + 32 * u]; s += v[u]; }
#pragma unroll
    for (int o = 16; o > 0; o >>= 1) s += __shfl_xor_sync(0xffffffffu, s, o);
    float m = s * (1.f / 256.f);
    float ss = 0.f;
#pragma unroll
    for (int u = 0; u < 8; u++) { float d = v[u] - m; ss += d * d; }
#pragma unroll
    for (int o = 16; o > 0; o >>= 1) ss += __shfl_xor_sync(0xffffffffu, ss, o);
    if (lane == 0) {
        g_stats[2 * warp + 0] = m;
        g_stats[2 * warp + 1] = rsqrtf(ss * (1.f / 256.f) + LNEPS);
    }
}

// ---------------- LN(inputs) + column sums L ----------------
__global__ void __launch_bounds__(256)
k_lnx(const float* __restrict__ x, const float* __restrict__ g,
      const float* __restrict__ b) {
    int bb = blockIdx.x, jc = blockIdx.y;     // grid (32, 32)
    int t = threadIdx.x;
    float gg = g[t], bv = b[t];
    int row0 = bb * 4096 + jc * 128;
    float csum = 0.f;
#pragma unroll 4
    for (int r = 0; r < 128; r++) {
        int row = row0 + r;
        float m = g_stats[2 * row], rs = g_stats[2 * row + 1];
        float v = x[(size_t)row * 256 + t];
        float o = (v - m) * rs * gg + bv;
        g_lnx[(size_t)row * 256 + t] = o;
        csum += o;
    }
    atomicAdd(&g_L[bb * 256 + t], csum);
}

// ---------------- P_h = Wq_h^T @ Wk_h (once) ----------------
__global__ void __launch_bounds__(256)
k_pcomp(const float* __restrict__ Wq, const float* __restrict__ Wk) {
    int h = blockIdx.x, et = blockIdx.y, ct = blockIdx.z;
    int e0 = et * 64, c0 = ct * 64;
    int t = threadIdx.x;
    int tx = t & 15, ty = t >> 4;

    __shared__ float Qs[64][65];
    __shared__ float Ks[64][65];
    int d = t >> 2, sg = (t & 3) * 16;
#pragma unroll
    for (int q = 0; q < 4; q++) {
        float4 vq = *(const float4*)(Wq + (size_t)(h * 64 + d) * 256 + e0 + sg + q * 4);
        Qs[d][sg + q * 4 + 0] = vq.x; Qs[d][sg + q * 4 + 1] = vq.y;
        Qs[d][sg + q * 4 + 2] = vq.z; Qs[d][sg + q * 4 + 3] = vq.w;
        float4 vk = *(const float4*)(Wk + (size_t)(h * 64 + d) * 256 + c0 + sg + q * 4);
        Ks[d][sg + q * 4 + 0] = vk.x; Ks[d][sg + q * 4 + 1] = vk.y;
        Ks[d][sg + q * 4 + 2] = vk.z; Ks[d][sg + q * 4 + 3] = vk.w;
    }
    __syncthreads();
    float acc[4][4];
#pragma unroll
    for (int i = 0; i < 4; i++)
#pragma unroll
        for (int j = 0; j < 4; j++) acc[i][j] = 0.f;
    for (int dd = 0; dd < 64; dd++) {
        float a[4], bb[4];
#pragma unroll
        for (int i = 0; i < 4; i++) a[i] = Qs[dd][ty + 16 * i];
#pragma unroll
        for (int j = 0; j < 4; j++) bb[j] = Ks[dd][tx + 16 * j];
#pragma unroll
        for (int i = 0; i < 4; i++)
#pragma unroll
            for (int j = 0; j < 4; j++) acc[i][j] += a[i] * bb[j];
    }
#pragma unroll
    for (int i = 0; i < 4; i++)
#pragma unroll
        for (int j = 0; j < 4; j++)
            g_P[(size_t)h * 65536 + (size_t)(e0 + ty + 16 * i) * 256 + c0 + tx + 16 * j] = acc[i][j];
}

// ---------------- LN(fillers) + zero rowsum (+copy cond on iter0) ----------
__global__ void k_lnfill(const float* __restrict__ g, const float* __restrict__ b,
                         const float* __restrict__ cond, int first) {
    int t = threadIdx.x;
    int gt = blockIdx.x * 256 + t;
    if (gt < 1024) g_rowsum[gt] = 0.f;

    int row  = blockIdx.x * 8 + (t >> 5);   // 256 rows
    int lane = t & 31;
    const float* r = (first ? cond : g_fill) + (size_t)row * 256;
    float v[8];
    float s = 0.f;
#pragma unroll
    for (int u = 0; u < 8; u++) { v[u] = r[lane + 32 * u]; s += v[u]; }
#pragma unroll
    for (int o = 16; o > 0; o >>= 1) s += __shfl_xor_sync(0xffffffffu, s, o);
    float m = s * (1.f / 256.f);
    float ss = 0.f;
#pragma unroll
    for (int u = 0; u < 8; u++) { float d = v[u] - m; ss += d * d; }
#pragma unroll
    for (int o = 16; o > 0; o >>= 1) ss += __shfl_xor_sync(0xffffffffu, ss, o);
    float rstd = rsqrtf(ss * (1.f / 256.f) + LNEPS);
#pragma unroll
    for (int u = 0; u < 8; u++) {
        int c = lane + 32 * u;
        if (first) g_fill[row * 256 + c] = v[u];
        g_f[row * 256 + c] = (v[u] - m) * rstd * g[c] + b[c];
    }
}

// ---------------- t = SCALE * f @ P_h ----------------
__global__ void __launch_bounds__(256)
k_tgemm() {
    int b = blockIdx.x, ct = blockIdx.y;
    int c0 = ct * 64;
    int t = threadIdx.x;
    int ihx = t >> 3, c8 = (t & 7) * 8;
    int h = ihx & 3, i = ihx >> 2;

    __shared__ float fs[2048];
    __shared__ __align__(16) float Ps[4][32][68];

#pragma unroll
    for (int q = 0; q < 8; q++) fs[t + 256 * q] = g_f[b * 2048 + t + 256 * q];

    unsigned long long acc[4] = {0ull, 0ull, 0ull, 0ull};

    for (int ec = 0; ec < 8; ec++) {
        int e0 = ec * 32;
        __syncthreads();
#pragma unroll
        for (int q = 0; q < 8; q++) {
            int idx = t + 256 * q;
            int hh = idx >> 9, e = (idx >> 4) & 31, sg = idx & 15;
            float4 v = *(const float4*)(g_P + (size_t)hh * 65536 +
                                        (size_t)(e0 + e) * 256 + c0 + sg * 4);
            *(float4*)&Ps[hh][e][sg * 4] = v;
        }
        __syncthreads();
#pragma unroll
        for (int e = 0; e < 32; e++) {
            unsigned long long a = bcast2(fs[i * 256 + e0 + e]);
            ulonglong2 p0 = *(const ulonglong2*)&Ps[h][e][c8];
            ulonglong2 p1 = *(const ulonglong2*)&Ps[h][e][c8 + 4];
            acc[0] = ffma2(a, p0.x, acc[0]);
            acc[1] = ffma2(a, p0.y, acc[1]);
            acc[2] = ffma2(a, p1.x, acc[2]);
            acc[3] = ffma2(a, p1.y, acc[3]);
        }
    }
    int row = b * 32 + ihx;
#pragma unroll
    for (int q = 0; q < 4; q++) {
        g_t[(size_t)row * 256 + c0 + c8 + 2 * q]     = SCALEF * lo2(acc[q]);
        g_t[(size_t)row * 256 + c0 + c8 + 2 * q + 1] = SCALEF * hi2(acc[q]);
    }
}

// ---------------- fused: dots + inverted softmax + u-accumulation ------------
// grid (32 b, 16 js of 256 j), 256 threads. attn never leaves smem.
__global__ void __launch_bounds__(256)
k_fused(int last, float* __restrict__ attn_out) {
    int b = blockIdx.x, js = blockIdx.y;
    int t = threadIdx.x;
    int tj = t & 31, tih = t >> 5;            // phase1: 4 j each / 4 ih each
                                              // phase2: tj=4c-group, tih=4 ih

    __shared__ __align__(16) unsigned long long t2[32][32];   // 8KB
    __shared__ __align__(16) float bsu[4224];                 // union 16.9KB
    __shared__ __align__(16) float dsm[32][132];              // 16.9KB
    __shared__ __align__(16) unsigned long long A2[32][16];   // 4KB
    float (*Bs)[132]  = (float(*)[132])bsu;                   // [c][j]
    float (*Bs2)[260] = (float(*)[260])bsu;                   // [j][c]

    const float* lnxb = g_lnx + (size_t)b * 4096 * 256;

    unsigned long long uacc[4][4];
#pragma unroll
    for (int ii = 0; ii < 4; ii++)
#pragma unroll
        for (int q = 0; q < 4; q++) uacc[ii][q] = 0ull;
    float rs_local = 0.f;

    for (int sc = 0; sc < 2; sc++) {
        int j0 = js * 256 + sc * 128;

        // ---------- phase 1: dots ----------
        unsigned long long acc[4][2];
#pragma unroll
        for (int ii = 0; ii < 4; ii++) { acc[ii][0] = 0ull; acc[ii][1] = 0ull; }

        for (int cc = 0; cc < 8; cc++) {
            int c0 = cc * 32;
            __syncthreads();
#pragma unroll
            for (int q = 0; q < 4; q++) {
                int idx = t + 256 * q;
                int ih = idx >> 5, c = idx & 31;
                t2[ih][c] = bcast2(g_t[(size_t)(b * 32 + ih) * 256 + c0 + c]);
            }
            {
                int jr = t & 127, hf = (t >> 7) * 16;
                const float* src = lnxb + (size_t)(j0 + jr) * 256 + c0 + hf;
#pragma unroll
                for (int q = 0; q < 4; q++) {
                    float4 v = *(const float4*)(src + q * 4);
                    Bs[hf + q * 4 + 0][jr] = v.x;
                    Bs[hf + q * 4 + 1][jr] = v.y;
                    Bs[hf + q * 4 + 2][jr] = v.z;
                    Bs[hf + q * 4 + 3][jr] = v.w;
                }
            }
            __syncthreads();
#pragma unroll
            for (int c = 0; c < 32; c += 2) {
                ulonglong2 pa = *(const ulonglong2*)&Bs[c][tj * 4];
                ulonglong2 pb = *(const ulonglong2*)&Bs[c + 1][tj * 4];
#pragma unroll
                for (int ii = 0; ii < 4; ii++) {
                    ulonglong2 av = *(const ulonglong2*)&t2[tih + 8 * ii][c];
                    acc[ii][0] = ffma2(av.x, pa.x, acc[ii][0]);
                    acc[ii][1] = ffma2(av.x, pa.y, acc[ii][1]);
                    acc[ii][0] = ffma2(av.y, pb.x, acc[ii][0]);
                    acc[ii][1] = ffma2(av.y, pb.y, acc[ii][1]);
                }
            }
        }
        __syncthreads();
#pragma unroll
        for (int ii = 0; ii < 4; ii++)
            *(float4*)&dsm[tih + 8 * ii][tj * 4] = make_float4(
                lo2(acc[ii][0]), hi2(acc[ii][0]), lo2(acc[ii][1]), hi2(acc[ii][1]));
        __syncthreads();

        // ---------- softmax per column j ----------
        if (t < 128) {
            float vcol[32], mx = -1e30f;
#pragma unroll
            for (int ih = 0; ih < 32; ih++) { vcol[ih] = dsm[ih][t]; mx = fmaxf(mx, vcol[ih]); }
            float sum = 0.f;
#pragma unroll
            for (int ih = 0; ih < 32; ih++) { vcol[ih] = __expf(vcol[ih] - mx); sum += vcol[ih]; }
            float inv = 1.f / sum;
#pragma unroll
            for (int ih = 0; ih < 32; ih++) { vcol[ih] *= inv; dsm[ih][t] = vcol[ih]; }
            if (last) {
#pragma unroll
                for (int i = 0; i < 8; i++) {
                    float v = 0.25f * (vcol[4 * i] + vcol[4 * i + 1] +
                                       vcol[4 * i + 2] + vcol[4 * i + 3]);
                    attn_out[((size_t)b * 8 + i) * 4096 + j0 + t] = v;
                }
            }
        }
        __syncthreads();
        if (t < 32) {
            float s = 0.f;
#pragma unroll 8
            for (int j = 0; j < 128; j++) s += dsm[t][j];
            rs_local += s;
        }

        // ---------- phase 2: u += attn * lnx ----------
        for (int jt = 0; jt < 8; jt++) {
            __syncthreads();
#pragma unroll
            for (int q = 0; q < 4; q++) {
                int idx = t + 256 * q;
                int r = idx >> 6, s4 = idx & 63;
                *(float4*)&Bs2[r][s4 * 4] =
                    *(const float4*)(lnxb + (size_t)(j0 + jt * 16 + r) * 256 + s4 * 4);
            }
#pragma unroll
            for (int q = 0; q < 2; q++) {
                int idx = t + 256 * q;
                int ih = idx >> 4, j = idx & 15;
                A2[ih][j] = bcast2(dsm[ih][jt * 16 + j]);
            }
            __syncthreads();
#pragma unroll
            for (int j = 0; j < 16; j++) {
                ulonglong2 p0 = *(const ulonglong2*)&Bs2[j][tj * 4];
                ulonglong2 p1 = *(const ulonglong2*)&Bs2[j][128 + tj * 4];
#pragma unroll
                for (int ii = 0; ii < 4; ii++) {
                    unsigned long long a = A2[tih * 4 + ii][j];
                    uacc[ii][0] = ffma2(a, p0.x, uacc[ii][0]);
                    uacc[ii][1] = ffma2(a, p0.y, uacc[ii][1]);
                    uacc[ii][2] = ffma2(a, p1.x, uacc[ii][2]);
                    uacc[ii][3] = ffma2(a, p1.y, uacc[ii][3]);
                }
            }
        }
    }

    // write u partials (slice js, overwrite: no zeroing needed)
#pragma unroll
    for (int ii = 0; ii < 4; ii++) {
        int ih = tih * 4 + ii;
        float* dst = g_upart + ((size_t)(js * 1024) + b * 32 + ih) * 256;
        *(float4*)&dst[tj * 4] = make_float4(
            lo2(uacc[ii][0]), hi2(uacc[ii][0]), lo2(uacc[ii][1]), hi2(uacc[ii][1]));
        *(float4*)&dst[128 + tj * 4] = make_float4(
            lo2(uacc[ii][2]), hi2(uacc[ii][2]), lo2(uacc[ii][3]), hi2(uacc[ii][3]));
    }
    if (t < 32) atomicAdd(&g_rowsum[b * 32 + t], rs_local);
}

// ---------------- upd = ((Σu + eps·L)/denom) @ Wv_h^T ----------------
__global__ void __launch_bounds__(256)
k_updproj(const float* __restrict__ Wv) {
    int b = blockIdx.x, dh2 = blockIdx.y;
    int t = threadIdx.x;
    int ihx = t >> 3, dq = (t & 7) * 4;
    int h = ihx & 3, i = ihx >> 2;
    int dbase = dh2 * 32;

    __shared__ __align__(16) float ss[32][256];
    __shared__ float Wvs[4][32][16];
    __shared__ float inv_s[32];

    if (t < 32) inv_s[t] = 1.f / (g_rowsum[b * 32 + t] + 4096.f * EPSF);
    __syncthreads();

#pragma unroll
    for (int q = 0; q < 8; q++) {
        int idx = t + 256 * q;
        int ih = idx >> 6, s4 = idx & 63;
        float4 Lv = *(const float4*)(g_L + b * 256 + s4 * 4);
        float4 a = make_float4(Lv.x * EPSF, Lv.y * EPSF, Lv.z * EPSF, Lv.w * EPSF);
#pragma unroll
        for (int p = 0; p < 16; p++) {
            float4 u = *(const float4*)(g_upart + ((size_t)(p * 1024) + b * 32 + ih) * 256 + s4 * 4);
            a.x += u.x; a.y += u.y; a.z += u.z; a.w += u.w;
        }
        float iv = inv_s[ih];
        a.x *= iv; a.y *= iv; a.z *= iv; a.w *= iv;
        *(float4*)&ss[ih][s4 * 4] = a;
    }

    float acc[4] = {0.f, 0.f, 0.f, 0.f};
    for (int cc = 0; cc < 16; cc++) {
        int c0 = cc * 16;
        __syncthreads();
#pragma unroll
        for (int q = 0; q < 8; q++) {
            int idx = t + 256 * q;
            int hh = idx >> 9, dd = (idx >> 4) & 31, c = idx & 15;
            Wvs[hh][dd][c] = Wv[(size_t)(hh * 64 + dbase + dd) * 256 + c0 + c];
        }
        __syncthreads();
#pragma unroll
        for (int c4 = 0; c4 < 4; c4++) {
            float4 sv = *(const float4*)&ss[ihx][c0 + c4 * 4];
#pragma unroll
            for (int k = 0; k < 4; k++) {
                const float* w = &Wvs[h][dq + k][c4 * 4];
                acc[k] += sv.x * w[0] + sv.y * w[1] + sv.z * w[2] + sv.w * w[3];
            }
        }
    }
#pragma unroll
    for (int k = 0; k < 4; k++)
        g_upd[(size_t)(b * 8 + i) * 256 + h * 64 + dbase + dq + k] = acc[k];
}

// ---------------- combined GRU gate GEMMs ----------------
__global__ void __launch_bounds__(256)
k_gates(const float* __restrict__ W_ih, const float* __restrict__ W_hh,
        const float* __restrict__ b_ih, const float* __restrict__ b_hh) {
    int mode = blockIdx.z;
    const float* A    = mode ? g_fill : g_upd;
    const float* W    = mode ? W_hh : W_ih;
    const float* bias = mode ? b_hh : b_ih;
    float* C = g_gates + mode * 196608;

    __shared__ float As[64][17];
    __shared__ float Bsx[64][17];
    int t = threadIdx.x;
    int row0 = blockIdx.x * 64, col0 = blockIdx.y * 64;
    int tx = t & 15, ty = t >> 4;

    float acc[4][4];
#pragma unroll
    for (int i = 0; i < 4; i++)
#pragma unroll
        for (int j = 0; j < 4; j++) acc[i][j] = 0.f;

    for (int k0 = 0; k0 < 256; k0 += 16) {
        __syncthreads();
        {
            int row = t >> 2, kp = t & 3;
            float4 a4 = *(const float4*)(A + (size_t)(row0 + row) * 256 + k0 + kp * 4);
            As[row][kp * 4 + 0] = a4.x; As[row][kp * 4 + 1] = a4.y;
            As[row][kp * 4 + 2] = a4.z; As[row][kp * 4 + 3] = a4.w;
            float4 b4 = *(const float4*)(W + (size_t)(col0 + row) * 256 + k0 + kp * 4);
            Bsx[row][kp * 4 + 0] = b4.x; Bsx[row][kp * 4 + 1] = b4.y;
            Bsx[row][kp * 4 + 2] = b4.z; Bsx[row][kp * 4 + 3] = b4.w;
        }
        __syncthreads();
#pragma unroll
        for (int kk = 0; kk < 16; kk++) {
            float a[4], bb[4];
#pragma unroll
            for (int i = 0; i < 4; i++) a[i]  = As[ty + 16 * i][kk];
#pragma unroll
            for (int j = 0; j < 4; j++) bb[j] = Bsx[tx + 16 * j][kk];
#pragma unroll
            for (int i = 0; i < 4; i++)
#pragma unroll
                for (int j = 0; j < 4; j++) acc[i][j] += a[i] * bb[j];
        }
    }
#pragma unroll
    for (int i = 0; i < 4; i++)
#pragma unroll
        for (int j = 0; j < 4; j++)
            C[(size_t)(row0 + ty + 16 * i) * 768 + col0 + tx + 16 * j] =
                acc[i][j] + bias[col0 + tx + 16 * j];
}

// ---------------- GRU elementwise ----------------
__global__ void k_gru() {
    int idx = blockIdx.x * blockDim.x + threadIdx.x;
    int r = idx >> 8, c = idx & 255;
    const float* gi = g_gates + (size_t)r * 768;
    const float* gh = g_gates + 196608 + (size_t)r * 768;
    float ir = gi[c], iz = gi[c + 256], in = gi[c + 512];
    float hr = gh[c], hz = gh[c + 256], hn = gh[c + 512];
    float rr = 1.f / (1.f + expf(-(ir + hr)));
    float zz = 1.f / (1.f + expf(-(iz + hz)));
    float nn = tanhf(in + rr * hn);
    float hp = g_fill[idx];
    g_fill[idx] = (1.f - zz) * nn + zz * hp;
}

__global__ void k_copyout(float* __restrict__ dst) {
    int idx = blockIdx.x * blockDim.x + threadIdx.x;
    dst[idx] = g_fill[idx];
}

// ---------------- launcher ----------------
extern "C" void kernel_launch(void* const* d_in, const int* in_sizes, int n_in,
                              void* d_out, int out_size) {
    const float* inputs = (const float*)d_in[0];
    const float* cond   = (const float*)d_in[1];
    const float* Wq     = (const float*)d_in[2];
    const float* Wk     = (const float*)d_in[3];
    const float* Wv     = (const float*)d_in[4];
    const float* W_ih   = (const float*)d_in[5];
    const float* W_hh   = (const float*)d_in[6];
    const float* b_ih   = (const float*)d_in[7];
    const float* b_hh   = (const float*)d_in[8];
    const float* lig    = (const float*)d_in[9];
    const float* lib    = (const float*)d_in[10];
    const float* lfg    = (const float*)d_in[11];
    const float* lfb    = (const float*)d_in[12];
    float* out = (float*)d_out;

    k_rowstats<<<16384, 256>>>(inputs);                         // 1
    k_lnx<<<dim3(32, 32), 256>>>(inputs, lig, lib);             // 2
    k_pcomp<<<dim3(4, 4, 4), 256>>>(Wq, Wk);                    // 3

    for (int it = 0; it < 3; it++) {
        k_lnfill<<<32, 256>>>(lfg, lfb, cond, it == 0);         // 4
        k_tgemm<<<dim3(32, 4), 256>>>();                        // 5
        k_fused<<<dim3(32, 16), 256>>>(it == 2 ? 1 : 0, out + 65536);  // 6 (ncu)
        k_updproj<<<dim3(32, 2), 256>>>(Wv);                    // 7
        k_gates<<<dim3(4, 12, 2), 256>>>(W_ih, W_hh, b_ih, b_hh); // 8
        k_gru<<<256, 256>>>();                                  // 9
    }
    k_copyout<<<64, 1024>>>(out);
}

// round 10
// speedup vs baseline: 2.1374x; 1.0891x over previous
#include <cuda_runtime.h>
#include <cstdint>
#include <math.h>

#define SCALEF 0.125f     // DH^-0.5
#define EPSF   1e-8f
#define LNEPS  1e-5f

// -------- scratch (device globals: allocation-free) --------
__device__ float g_stats[2 * 131072];     // per-row mean,rstd of inputs
__device__ float g_lnx[33554432];         // LN(inputs) [b][j][256]
__device__ float g_L[8192];               // L[b][c] = sum_j lnx
__device__ float g_P[4 * 256 * 256];      // P_h = Wq_h^T Wk_h
__device__ float g_t[1024 * 256];         // t[(b,ih)][c] (SCALE folded)
__device__ float g_upart[16 * 1024 * 256];// u partials [js][(b,ih)][c]
__device__ float g_rowsum[1024];          // [b][ih]
__device__ float g_fill[65536];           // fillers
__device__ float g_f[65536];              // LN(fillers)
__device__ float g_upd[65536];            // updates
__device__ float g_gates[2 * 256 * 768];  // [gi|gh]

// ---------------- packed f32x2 helpers ----------------
__device__ __forceinline__ unsigned long long ffma2(unsigned long long a,
                                                    unsigned long long b,
                                                    unsigned long long c) {
    unsigned long long d;
    asm("fma.rn.f32x2 %0, %1, %2, %3;" : "=l"(d) : "l"(a), "l"(b), "l"(c));
    return d;
}
__device__ __forceinline__ unsigned long long bcast2(float x) {
    unsigned u = __float_as_uint(x);
    return ((unsigned long long)u << 32) | (unsigned long long)u;
}
__device__ __forceinline__ float lo2(unsigned long long v) { return __uint_as_float((unsigned)v); }
__device__ __forceinline__ float hi2(unsigned long long v) { return __uint_as_float((unsigned)(v >> 32)); }

// ---------------- row stats (also zero g_L) ----------------
__global__ void k_rowstats(const float* __restrict__ x) {
    int gid = blockIdx.x * blockDim.x + threadIdx.x;
    if (gid < 8192) g_L[gid] = 0.f;
    int warp = gid >> 5;
    int lane = threadIdx.x & 31;
    const float* r = x + (size_t)warp * 256;
    float v[8];
    float s = 0.f;
#pragma unroll
    for (int u = 0; u < 8; u++) { v[u] = r[lane + 32 * u]; s += v[u]; }
#pragma unroll
    for (int o = 16; o > 0; o >>= 1) s += __shfl_xor_sync(0xffffffffu, s, o);
    float m = s * (1.f / 256.f);
    float ss = 0.f;
#pragma unroll
    for (int u = 0; u < 8; u++) { float d = v[u] - m; ss += d * d; }
#pragma unroll
    for (int o = 16; o > 0; o >>= 1) ss += __shfl_xor_sync(0xffffffffu, ss, o);
    if (lane == 0) {
        g_stats[2 * warp + 0] = m;
        g_stats[2 * warp + 1] = rsqrtf(ss * (1.f / 256.f) + LNEPS);
    }
}

// ---------------- LN(inputs) + column sums L ----------------
__global__ void __launch_bounds__(256)
k_lnx(const float* __restrict__ x, const float* __restrict__ g,
      const float* __restrict__ b) {
    int bb = blockIdx.x, jc = blockIdx.y;     // grid (32, 32)
    int t = threadIdx.x;
    float gg = g[t], bv = b[t];
    int row0 = bb * 4096 + jc * 128;
    float csum = 0.f;
#pragma unroll 4
    for (int r = 0; r < 128; r++) {
        int row = row0 + r;
        float m = g_stats[2 * row], rs = g_stats[2 * row + 1];
        float v = x[(size_t)row * 256 + t];
        float o = (v - m) * rs * gg + bv;
        g_lnx[(size_t)row * 256 + t] = o;
        csum += o;
    }
    atomicAdd(&g_L[bb * 256 + t], csum);
}

// ---------------- P_h = Wq_h^T @ Wk_h (once) ----------------
__global__ void __launch_bounds__(256)
k_pcomp(const float* __restrict__ Wq, const float* __restrict__ Wk) {
    int h = blockIdx.x, et = blockIdx.y, ct = blockIdx.z;
    int e0 = et * 64, c0 = ct * 64;
    int t = threadIdx.x;
    int tx = t & 15, ty = t >> 4;

    __shared__ float Qs[64][65];
    __shared__ float Ks[64][65];
    int d = t >> 2, sg = (t & 3) * 16;
#pragma unroll
    for (int q = 0; q < 4; q++) {
        float4 vq = *(const float4*)(Wq + (size_t)(h * 64 + d) * 256 + e0 + sg + q * 4);
        Qs[d][sg + q * 4 + 0] = vq.x; Qs[d][sg + q * 4 + 1] = vq.y;
        Qs[d][sg + q * 4 + 2] = vq.z; Qs[d][sg + q * 4 + 3] = vq.w;
        float4 vk = *(const float4*)(Wk + (size_t)(h * 64 + d) * 256 + c0 + sg + q * 4);
        Ks[d][sg + q * 4 + 0] = vk.x; Ks[d][sg + q * 4 + 1] = vk.y;
        Ks[d][sg + q * 4 + 2] = vk.z; Ks[d][sg + q * 4 + 3] = vk.w;
    }
    __syncthreads();
    float acc[4][4];
#pragma unroll
    for (int i = 0; i < 4; i++)
#pragma unroll
        for (int j = 0; j < 4; j++) acc[i][j] = 0.f;
    for (int dd = 0; dd < 64; dd++) {
        float a[4], bb[4];
#pragma unroll
        for (int i = 0; i < 4; i++) a[i] = Qs[dd][ty + 16 * i];
#pragma unroll
        for (int j = 0; j < 4; j++) bb[j] = Ks[dd][tx + 16 * j];
#pragma unroll
        for (int i = 0; i < 4; i++)
#pragma unroll
            for (int j = 0; j < 4; j++) acc[i][j] += a[i] * bb[j];
    }
#pragma unroll
    for (int i = 0; i < 4; i++)
#pragma unroll
        for (int j = 0; j < 4; j++)
            g_P[(size_t)h * 65536 + (size_t)(e0 + ty + 16 * i) * 256 + c0 + tx + 16 * j] = acc[i][j];
}

// ---------------- LN(fillers) + zero rowsum (+copy cond on iter0) ----------
__global__ void k_lnfill(const float* __restrict__ g, const float* __restrict__ b,
                         const float* __restrict__ cond, int first) {
    int t = threadIdx.x;
    int gt = blockIdx.x * 256 + t;
    if (gt < 1024) g_rowsum[gt] = 0.f;

    int row  = blockIdx.x * 8 + (t >> 5);   // 256 rows
    int lane = t & 31;
    const float* r = (first ? cond : g_fill) + (size_t)row * 256;
    float v[8];
    float s = 0.f;
#pragma unroll
    for (int u = 0; u < 8; u++) { v[u] = r[lane + 32 * u]; s += v[u]; }
#pragma unroll
    for (int o = 16; o > 0; o >>= 1) s += __shfl_xor_sync(0xffffffffu, s, o);
    float m = s * (1.f / 256.f);
    float ss = 0.f;
#pragma unroll
    for (int u = 0; u < 8; u++) { float d = v[u] - m; ss += d * d; }
#pragma unroll
    for (int o = 16; o > 0; o >>= 1) ss += __shfl_xor_sync(0xffffffffu, ss, o);
    float rstd = rsqrtf(ss * (1.f / 256.f) + LNEPS);
#pragma unroll
    for (int u = 0; u < 8; u++) {
        int c = lane + 32 * u;
        if (first) g_fill[row * 256 + c] = v[u];
        g_f[row * 256 + c] = (v[u] - m) * rstd * g[c] + b[c];
    }
}

// ---------------- t = SCALE * f @ P_h ----------------
__global__ void __launch_bounds__(256)
k_tgemm() {
    int b = blockIdx.x, ct = blockIdx.y;
    int c0 = ct * 64;
    int t = threadIdx.x;
    int ihx = t >> 3, c8 = (t & 7) * 8;
    int h = ihx & 3, i = ihx >> 2;

    __shared__ float fs[2048];
    __shared__ __align__(16) float Ps[4][32][68];

#pragma unroll
    for (int q = 0; q < 8; q++) fs[t + 256 * q] = g_f[b * 2048 + t + 256 * q];

    unsigned long long acc[4] = {0ull, 0ull, 0ull, 0ull};

    for (int ec = 0; ec < 8; ec++) {
        int e0 = ec * 32;
        __syncthreads();
#pragma unroll
        for (int q = 0; q < 8; q++) {
            int idx = t + 256 * q;
            int hh = idx >> 9, e = (idx >> 4) & 31, sg = idx & 15;
            float4 v = *(const float4*)(g_P + (size_t)hh * 65536 +
                                        (size_t)(e0 + e) * 256 + c0 + sg * 4);
            *(float4*)&Ps[hh][e][sg * 4] = v;
        }
        __syncthreads();
#pragma unroll
        for (int e = 0; e < 32; e++) {
            unsigned long long a = bcast2(fs[i * 256 + e0 + e]);
            ulonglong2 p0 = *(const ulonglong2*)&Ps[h][e][c8];
            ulonglong2 p1 = *(const ulonglong2*)&Ps[h][e][c8 + 4];
            acc[0] = ffma2(a, p0.x, acc[0]);
            acc[1] = ffma2(a, p0.y, acc[1]);
            acc[2] = ffma2(a, p1.x, acc[2]);
            acc[3] = ffma2(a, p1.y, acc[3]);
        }
    }
    int row = b * 32 + ihx;
#pragma unroll
    for (int q = 0; q < 4; q++) {
        g_t[(size_t)row * 256 + c0 + c8 + 2 * q]     = SCALEF * lo2(acc[q]);
        g_t[(size_t)row * 256 + c0 + c8 + 2 * q + 1] = SCALEF * hi2(acc[q]);
    }
}

// ---------------- fused: dots + inverted softmax + u-accumulation ------------
// grid (32 b, 16 js of 256 j), 128 threads. 8 ih x 8 j register tile:
// warp = ih-group -> broadcast a-operand loads; FFMA2-issue bound.
__global__ void __launch_bounds__(128)
k_fused(int last, float* __restrict__ attn_out) {
    extern __shared__ float dynsm[];
    float* dsm = dynsm;                                  // [32][260] dots/attn
    float* Bs  = dynsm + 32 * 260;                       // [16][260] lnx tile (both phases)
    unsigned long long* t2 =
        (unsigned long long*)(dynsm + 32 * 260 + 16 * 260);  // [32][16] u64 (a-operand)

    int b = blockIdx.x, js = blockIdx.y;
    int t = threadIdx.x;
    int ihg = t >> 5;          // warp id = ih-group (8 ih)
    int jg  = t & 31;          // phase1: 8-j group; phase2: 8-c group
    int j0 = js * 256;

    const float* lnxb = g_lnx + (size_t)b * 4096 * 256;

    unsigned long long acc[8][4];
#pragma unroll
    for (int ii = 0; ii < 8; ii++)
#pragma unroll
        for (int q = 0; q < 4; q++) acc[ii][q] = 0ull;

    // ---------- phase 1: dots[ih][j] ----------
    for (int cc = 0; cc < 16; cc++) {
        int c0 = cc * 16;
        __syncthreads();
        {   // t2: 32 ih x 16 c (pre-broadcast u64)
            int ih = t >> 2, cq = (t & 3) * 4;
            float4 v = *(const float4*)(g_t + (size_t)(b * 32 + ih) * 256 + c0 + cq);
            t2[ih * 16 + cq + 0] = bcast2(v.x);
            t2[ih * 16 + cq + 1] = bcast2(v.y);
            t2[ih * 16 + cq + 2] = bcast2(v.z);
            t2[ih * 16 + cq + 3] = bcast2(v.w);
        }
        // Bs: [c][j] transposed lnx tile, 16 c x 256 j
#pragma unroll
        for (int q = 0; q < 8; q++) {
            int idx = t + 128 * q;
            int j = idx >> 2, f4 = (idx & 3) * 4;
            float4 v = *(const float4*)(lnxb + (size_t)(j0 + j) * 256 + c0 + f4);
            Bs[(f4 + 0) * 260 + j] = v.x;
            Bs[(f4 + 1) * 260 + j] = v.y;
            Bs[(f4 + 2) * 260 + j] = v.z;
            Bs[(f4 + 3) * 260 + j] = v.w;
        }
        __syncthreads();
#pragma unroll
        for (int c = 0; c < 16; c++) {
            ulonglong2 b0 = *(const ulonglong2*)&Bs[c * 260 + jg * 8];
            ulonglong2 b1 = *(const ulonglong2*)&Bs[c * 260 + jg * 8 + 4];
#pragma unroll
            for (int ii = 0; ii < 8; ii++) {
                unsigned long long a = t2[(ihg * 8 + ii) * 16 + c];
                acc[ii][0] = ffma2(a, b0.x, acc[ii][0]);
                acc[ii][1] = ffma2(a, b0.y, acc[ii][1]);
                acc[ii][2] = ffma2(a, b1.x, acc[ii][2]);
                acc[ii][3] = ffma2(a, b1.y, acc[ii][3]);
            }
        }
    }
    __syncthreads();
#pragma unroll
    for (int ii = 0; ii < 8; ii++) {
        float* row = &dsm[(ihg * 8 + ii) * 260 + jg * 8];
        *(float4*)row       = make_float4(lo2(acc[ii][0]), hi2(acc[ii][0]),
                                          lo2(acc[ii][1]), hi2(acc[ii][1]));
        *(float4*)(row + 4) = make_float4(lo2(acc[ii][2]), hi2(acc[ii][2]),
                                          lo2(acc[ii][3]), hi2(acc[ii][3]));
    }
    __syncthreads();

    // ---------- softmax over 32 (slot,head) per column ----------
#pragma unroll
    for (int col = 0; col < 2; col++) {
        int j = t + col * 128;
        float vcol[32], mx = -1e30f;
#pragma unroll
        for (int ih = 0; ih < 32; ih++) { vcol[ih] = dsm[ih * 260 + j]; mx = fmaxf(mx, vcol[ih]); }
        float sum = 0.f;
#pragma unroll
        for (int ih = 0; ih < 32; ih++) { vcol[ih] = __expf(vcol[ih] - mx); sum += vcol[ih]; }
        float inv = 1.f / sum;
#pragma unroll
        for (int ih = 0; ih < 32; ih++) { vcol[ih] *= inv; dsm[ih * 260 + j] = vcol[ih]; }
        if (last) {
#pragma unroll
            for (int i = 0; i < 8; i++)
                attn_out[((size_t)b * 8 + i) * 4096 + j0 + j] =
                    0.25f * (vcol[4 * i] + vcol[4 * i + 1] + vcol[4 * i + 2] + vcol[4 * i + 3]);
        }
    }

    // ---------- phase 2: u[ih][c] += attn[ih][j] * lnx[j][c] ----------
    unsigned long long* A2 = t2;
    float rs = 0.f;
#pragma unroll
    for (int ii = 0; ii < 8; ii++)
#pragma unroll
        for (int q = 0; q < 4; q++) acc[ii][q] = 0ull;

    for (int jt = 0; jt < 16; jt++) {
        int jb = jt * 16;
        __syncthreads();
        // Bs: [j][c] 16 j x 256 c
#pragma unroll
        for (int q = 0; q < 8; q++) {
            int idx = t + 128 * q;
            int r = idx >> 6, f4 = idx & 63;
            *(float4*)&Bs[r * 260 + f4 * 4] =
                *(const float4*)(lnxb + (size_t)(j0 + jb + r) * 256 + f4 * 4);
        }
        {   // A2 pack + rowsum partial (thread's ih fixed = t>>2)
            int ih = t >> 2, jq = (t & 3) * 4;
#pragma unroll
            for (int k = 0; k < 4; k++) {
                float a = dsm[ih * 260 + jb + jq + k];
                rs += a;
                A2[ih * 16 + jq + k] = bcast2(a);
            }
        }
        __syncthreads();
#pragma unroll
        for (int j = 0; j < 16; j++) {
            ulonglong2 b0 = *(const ulonglong2*)&Bs[j * 260 + jg * 8];
            ulonglong2 b1 = *(const ulonglong2*)&Bs[j * 260 + jg * 8 + 4];
#pragma unroll
            for (int ii = 0; ii < 8; ii++) {
                unsigned long long a = A2[(ihg * 8 + ii) * 16 + j];
                acc[ii][0] = ffma2(a, b0.x, acc[ii][0]);
                acc[ii][1] = ffma2(a, b0.y, acc[ii][1]);
                acc[ii][2] = ffma2(a, b1.x, acc[ii][2]);
                acc[ii][3] = ffma2(a, b1.y, acc[ii][3]);
            }
        }
    }

    // u partials (slice js; overwrite, no zeroing)
#pragma unroll
    for (int ii = 0; ii < 8; ii++) {
        float* dst = g_upart + ((size_t)(js * 1024) + b * 32 + ihg * 8 + ii) * 256 + jg * 8;
        *(float4*)dst       = make_float4(lo2(acc[ii][0]), hi2(acc[ii][0]),
                                          lo2(acc[ii][1]), hi2(acc[ii][1]));
        *(float4*)(dst + 4) = make_float4(lo2(acc[ii][2]), hi2(acc[ii][2]),
                                          lo2(acc[ii][3]), hi2(acc[ii][3]));
    }
    // rowsum: reduce 4 threads sharing one ih, then one atomic
    rs += __shfl_xor_sync(0xffffffffu, rs, 1);
    rs += __shfl_xor_sync(0xffffffffu, rs, 2);
    if ((t & 3) == 0) atomicAdd(&g_rowsum[b * 32 + (t >> 2)], rs);
}

// ---------------- upd = ((Σu + eps·L)/denom) @ Wv_h^T ----------------
__global__ void __launch_bounds__(256)
k_updproj(const float* __restrict__ Wv) {
    int b = blockIdx.x, dh2 = blockIdx.y;
    int t = threadIdx.x;
    int ihx = t >> 3, dq = (t & 7) * 4;
    int h = ihx & 3, i = ihx >> 2;
    int dbase = dh2 * 32;

    __shared__ __align__(16) float ss[32][256];
    __shared__ float Wvs[4][32][16];
    __shared__ float inv_s[32];

    if (t < 32) inv_s[t] = 1.f / (g_rowsum[b * 32 + t] + 4096.f * EPSF);
    __syncthreads();

#pragma unroll
    for (int q = 0; q < 8; q++) {
        int idx = t + 256 * q;
        int ih = idx >> 6, s4 = idx & 63;
        float4 Lv = *(const float4*)(g_L + b * 256 + s4 * 4);
        float4 a = make_float4(Lv.x * EPSF, Lv.y * EPSF, Lv.z * EPSF, Lv.w * EPSF);
#pragma unroll
        for (int p = 0; p < 16; p++) {
            float4 u = *(const float4*)(g_upart + ((size_t)(p * 1024) + b * 32 + ih) * 256 + s4 * 4);
            a.x += u.x; a.y += u.y; a.z += u.z; a.w += u.w;
        }
        float iv = inv_s[ih];
        a.x *= iv; a.y *= iv; a.z *= iv; a.w *= iv;
        *(float4*)&ss[ih][s4 * 4] = a;
    }

    float acc[4] = {0.f, 0.f, 0.f, 0.f};
    for (int cc = 0; cc < 16; cc++) {
        int c0 = cc * 16;
        __syncthreads();
#pragma unroll
        for (int q = 0; q < 8; q++) {
            int idx = t + 256 * q;
            int hh = idx >> 9, dd = (idx >> 4) & 31, c = idx & 15;
            Wvs[hh][dd][c] = Wv[(size_t)(hh * 64 + dbase + dd) * 256 + c0 + c];
        }
        __syncthreads();
#pragma unroll
        for (int c4 = 0; c4 < 4; c4++) {
            float4 sv = *(const float4*)&ss[ihx][c0 + c4 * 4];
#pragma unroll
            for (int k = 0; k < 4; k++) {
                const float* w = &Wvs[h][dq + k][c4 * 4];
                acc[k] += sv.x * w[0] + sv.y * w[1] + sv.z * w[2] + sv.w * w[3];
            }
        }
    }
#pragma unroll
    for (int k = 0; k < 4; k++)
        g_upd[(size_t)(b * 8 + i) * 256 + h * 64 + dbase + dq + k] = acc[k];
}

// ---------------- combined GRU gate GEMMs ----------------
__global__ void __launch_bounds__(256)
k_gates(const float* __restrict__ W_ih, const float* __restrict__ W_hh,
        const float* __restrict__ b_ih, const float* __restrict__ b_hh) {
    int mode = blockIdx.z;
    const float* A    = mode ? g_fill : g_upd;
    const float* W    = mode ? W_hh : W_ih;
    const float* bias = mode ? b_hh : b_ih;
    float* C = g_gates + mode * 196608;

    __shared__ float As[64][17];
    __shared__ float Bsx[64][17];
    int t = threadIdx.x;
    int row0 = blockIdx.x * 64, col0 = blockIdx.y * 64;
    int tx = t & 15, ty = t >> 4;

    float acc[4][4];
#pragma unroll
    for (int i = 0; i < 4; i++)
#pragma unroll
        for (int j = 0; j < 4; j++) acc[i][j] = 0.f;

    for (int k0 = 0; k0 < 256; k0 += 16) {
        __syncthreads();
        {
            int row = t >> 2, kp = t & 3;
            float4 a4 = *(const float4*)(A + (size_t)(row0 + row) * 256 + k0 + kp * 4);
            As[row][kp * 4 + 0] = a4.x; As[row][kp * 4 + 1] = a4.y;
            As[row][kp * 4 + 2] = a4.z; As[row][kp * 4 + 3] = a4.w;
            float4 b4 = *(const float4*)(W + (size_t)(col0 + row) * 256 + k0 + kp * 4);
            Bsx[row][kp * 4 + 0] = b4.x; Bsx[row][kp * 4 + 1] = b4.y;
            Bsx[row][kp * 4 + 2] = b4.z; Bsx[row][kp * 4 + 3] = b4.w;
        }
        __syncthreads();
#pragma unroll
        for (int kk = 0; kk < 16; kk++) {
            float a[4], bb[4];
#pragma unroll
            for (int i = 0; i < 4; i++) a[i]  = As[ty + 16 * i][kk];
#pragma unroll
            for (int j = 0; j < 4; j++) bb[j] = Bsx[tx + 16 * j][kk];
#pragma unroll
            for (int i = 0; i < 4; i++)
#pragma unroll
                for (int j = 0; j < 4; j++) acc[i][j] += a[i] * bb[j];
        }
    }
#pragma unroll
    for (int i = 0; i < 4; i++)
#pragma unroll
        for (int j = 0; j < 4; j++)
            C[(size_t)(row0 + ty + 16 * i) * 768 + col0 + tx + 16 * j] =
                acc[i][j] + bias[col0 + tx + 16 * j];
}

// ---------------- GRU elementwise ----------------
__global__ void k_gru() {
    int idx = blockIdx.x * blockDim.x + threadIdx.x;
    int r = idx >> 8, c = idx & 255;
    const float* gi = g_gates + (size_t)r * 768;
    const float* gh = g_gates + 196608 + (size_t)r * 768;
    float ir = gi[c], iz = gi[c + 256], in = gi[c + 512];
    float hr = gh[c], hz = gh[c + 256], hn = gh[c + 512];
    float rr = 1.f / (1.f + expf(-(ir + hr)));
    float zz = 1.f / (1.f + expf(-(iz + hz)));
    float nn = tanhf(in + rr * hn);
    float hp = g_fill[idx];
    g_fill[idx] = (1.f - zz) * nn + zz * hp;
}

__global__ void k_copyout(float* __restrict__ dst) {
    int idx = blockIdx.x * blockDim.x + threadIdx.x;
    dst[idx] = g_fill[idx];
}

// ---------------- launcher ----------------
extern "C" void kernel_launch(void* const* d_in, const int* in_sizes, int n_in,
                              void* d_out, int out_size) {
    const float* inputs = (const float*)d_in[0];
    const float* cond   = (const float*)d_in[1];
    const float* Wq     = (const float*)d_in[2];
    const float* Wk     = (const float*)d_in[3];
    const float* Wv     = (const float*)d_in[4];
    const float* W_ih   = (const float*)d_in[5];
    const float* W_hh   = (const float*)d_in[6];
    const float* b_ih   = (const float*)d_in[7];
    const float* b_hh   = (const float*)d_in[8];
    const float* lig    = (const float*)d_in[9];
    const float* lib    = (const float*)d_in[10];
    const float* lfg    = (const float*)d_in[11];
    const float* lfb    = (const float*)d_in[12];
    float* out = (float*)d_out;

    const int FUSED_SMEM = (32 * 260 + 16 * 260) * 4 + 32 * 16 * 8;  // 54016 B
    cudaFuncSetAttribute(k_fused, cudaFuncAttributeMaxDynamicSharedMemorySize, FUSED_SMEM);

    k_rowstats<<<16384, 256>>>(inputs);                         // 1
    k_lnx<<<dim3(32, 32), 256>>>(inputs, lig, lib);             // 2
    k_pcomp<<<dim3(4, 4, 4), 256>>>(Wq, Wk);                    // 3

    for (int it = 0; it < 3; it++) {
        k_lnfill<<<32, 256>>>(lfg, lfb, cond, it == 0);         // 4
        k_tgemm<<<dim3(32, 4), 256>>>();                        // 5
        k_fused<<<dim3(32, 16), 128, FUSED_SMEM>>>(it == 2 ? 1 : 0, out + 65536);  // 6 (ncu)
        k_updproj<<<dim3(32, 2), 256>>>(Wv);                    // 7
        k_gates<<<dim3(4, 12, 2), 256>>>(W_ih, W_hh, b_ih, b_hh); // 8
        k_gru<<<256, 256>>>();                                  // 9
    }
    k_copyout<<<64, 1024>>>(out);
}

// round 11
// speedup vs baseline: 2.2640x; 1.0592x over previous
#include <cuda_runtime.h>
#include <cstdint>
#include <math.h>

#define SCALEF 0.125f     // DH^-0.5
#define EPSF   1e-8f
#define LNEPS  1e-5f

// -------- scratch (device globals: allocation-free) --------
__device__ float g_stats[2 * 131072];     // per-row mean,rstd of inputs
__device__ float g_lnx[33554432];         // LN(inputs) [b][j][256]
__device__ float g_L[8192];               // L[b][c] = sum_j lnx
__device__ float g_P[4 * 256 * 256];      // P_h = Wq_h^T Wk_h
__device__ float g_t[1024 * 256];         // t[(b,ih)][c] (SCALE folded)
__device__ float g_upart[32 * 1024 * 256];// u partials [js][(b,ih)][c]
__device__ float g_rowsum[1024];          // [b][ih]
__device__ float g_fill[65536];           // fillers
__device__ float g_f[65536];              // LN(fillers)
__device__ float g_upd[65536];            // updates
__device__ float g_gates[2 * 256 * 768];  // [gi|gh]

// ---------------- packed f32x2 helpers ----------------
__device__ __forceinline__ unsigned long long ffma2(unsigned long long a,
                                                    unsigned long long b,
                                                    unsigned long long c) {
    unsigned long long d;
    asm("fma.rn.f32x2 %0, %1, %2, %3;" : "=l"(d) : "l"(a), "l"(b), "l"(c));
    return d;
}
__device__ __forceinline__ unsigned long long bcast2(float x) {
    unsigned u = __float_as_uint(x);
    return ((unsigned long long)u << 32) | (unsigned long long)u;
}
__device__ __forceinline__ float lo2(unsigned long long v) { return __uint_as_float((unsigned)v); }
__device__ __forceinline__ float hi2(unsigned long long v) { return __uint_as_float((unsigned)(v >> 32)); }

// ---------------- row stats (also zero g_L) ----------------
__global__ void k_rowstats(const float* __restrict__ x) {
    int gid = blockIdx.x * blockDim.x + threadIdx.x;
    if (gid < 8192) g_L[gid] = 0.f;
    int warp = gid >> 5;
    int lane = threadIdx.x & 31;
    const float* r = x + (size_t)warp * 256;
    float v[8];
    float s = 0.f;
#pragma unroll
    for (int u = 0; u < 8; u++) { v[u] = r[lane + 32 * u]; s += v[u]; }
#pragma unroll
    for (int o = 16; o > 0; o >>= 1) s += __shfl_xor_sync(0xffffffffu, s, o);
    float m = s * (1.f / 256.f);
    float ss = 0.f;
#pragma unroll
    for (int u = 0; u < 8; u++) { float d = v[u] - m; ss += d * d; }
#pragma unroll
    for (int o = 16; o > 0; o >>= 1) ss += __shfl_xor_sync(0xffffffffu, ss, o);
    if (lane == 0) {
        g_stats[2 * warp + 0] = m;
        g_stats[2 * warp + 1] = rsqrtf(ss * (1.f / 256.f) + LNEPS);
    }
}

// ---------------- LN(inputs) + column sums L ----------------
__global__ void __launch_bounds__(256)
k_lnx(const float* __restrict__ x, const float* __restrict__ g,
      const float* __restrict__ b) {
    int bb = blockIdx.x, jc = blockIdx.y;     // grid (32, 32)
    int t = threadIdx.x;
    float gg = g[t], bv = b[t];
    int row0 = bb * 4096 + jc * 128;
    float csum = 0.f;
#pragma unroll 4
    for (int r = 0; r < 128; r++) {
        int row = row0 + r;
        float m = g_stats[2 * row], rs = g_stats[2 * row + 1];
        float v = x[(size_t)row * 256 + t];
        float o = (v - m) * rs * gg + bv;
        g_lnx[(size_t)row * 256 + t] = o;
        csum += o;
    }
    atomicAdd(&g_L[bb * 256 + t], csum);
}

// ---------------- P_h = Wq_h^T @ Wk_h (once) ----------------
__global__ void __launch_bounds__(256)
k_pcomp(const float* __restrict__ Wq, const float* __restrict__ Wk) {
    int h = blockIdx.x, et = blockIdx.y, ct = blockIdx.z;
    int e0 = et * 64, c0 = ct * 64;
    int t = threadIdx.x;
    int tx = t & 15, ty = t >> 4;

    __shared__ float Qs[64][65];
    __shared__ float Ks[64][65];
    int d = t >> 2, sg = (t & 3) * 16;
#pragma unroll
    for (int q = 0; q < 4; q++) {
        float4 vq = *(const float4*)(Wq + (size_t)(h * 64 + d) * 256 + e0 + sg + q * 4);
        Qs[d][sg + q * 4 + 0] = vq.x; Qs[d][sg + q * 4 + 1] = vq.y;
        Qs[d][sg + q * 4 + 2] = vq.z; Qs[d][sg + q * 4 + 3] = vq.w;
        float4 vk = *(const float4*)(Wk + (size_t)(h * 64 + d) * 256 + c0 + sg + q * 4);
        Ks[d][sg + q * 4 + 0] = vk.x; Ks[d][sg + q * 4 + 1] = vk.y;
        Ks[d][sg + q * 4 + 2] = vk.z; Ks[d][sg + q * 4 + 3] = vk.w;
    }
    __syncthreads();
    float acc[4][4];
#pragma unroll
    for (int i = 0; i < 4; i++)
#pragma unroll
        for (int j = 0; j < 4; j++) acc[i][j] = 0.f;
    for (int dd = 0; dd < 64; dd++) {
        float a[4], bb[4];
#pragma unroll
        for (int i = 0; i < 4; i++) a[i] = Qs[dd][ty + 16 * i];
#pragma unroll
        for (int j = 0; j < 4; j++) bb[j] = Ks[dd][tx + 16 * j];
#pragma unroll
        for (int i = 0; i < 4; i++)
#pragma unroll
            for (int j = 0; j < 4; j++) acc[i][j] += a[i] * bb[j];
    }
#pragma unroll
    for (int i = 0; i < 4; i++)
#pragma unroll
        for (int j = 0; j < 4; j++)
            g_P[(size_t)h * 65536 + (size_t)(e0 + ty + 16 * i) * 256 + c0 + tx + 16 * j] = acc[i][j];
}

// ---------------- LN(fillers) + zero rowsum (+copy cond on iter0) ----------
__global__ void k_lnfill(const float* __restrict__ g, const float* __restrict__ b,
                         const float* __restrict__ cond, int first) {
    int t = threadIdx.x;
    int gt = blockIdx.x * 256 + t;
    if (gt < 1024) g_rowsum[gt] = 0.f;

    int row  = blockIdx.x * 8 + (t >> 5);   // 256 rows
    int lane = t & 31;
    const float* r = (first ? cond : g_fill) + (size_t)row * 256;
    float v[8];
    float s = 0.f;
#pragma unroll
    for (int u = 0; u < 8; u++) { v[u] = r[lane + 32 * u]; s += v[u]; }
#pragma unroll
    for (int o = 16; o > 0; o >>= 1) s += __shfl_xor_sync(0xffffffffu, s, o);
    float m = s * (1.f / 256.f);
    float ss = 0.f;
#pragma unroll
    for (int u = 0; u < 8; u++) { float d = v[u] - m; ss += d * d; }
#pragma unroll
    for (int o = 16; o > 0; o >>= 1) ss += __shfl_xor_sync(0xffffffffu, ss, o);
    float rstd = rsqrtf(ss * (1.f / 256.f) + LNEPS);
#pragma unroll
    for (int u = 0; u < 8; u++) {
        int c = lane + 32 * u;
        if (first) g_fill[row * 256 + c] = v[u];
        g_f[row * 256 + c] = (v[u] - m) * rstd * g[c] + b[c];
    }
}

// ---------------- t = SCALE * f @ P_h ----------------
__global__ void __launch_bounds__(256)
k_tgemm() {
    int b = blockIdx.x, ct = blockIdx.y;
    int c0 = ct * 64;
    int t = threadIdx.x;
    int ihx = t >> 3, c8 = (t & 7) * 8;
    int h = ihx & 3, i = ihx >> 2;

    __shared__ float fs[2048];
    __shared__ __align__(16) float Ps[4][32][68];

#pragma unroll
    for (int q = 0; q < 8; q++) fs[t + 256 * q] = g_f[b * 2048 + t + 256 * q];

    unsigned long long acc[4] = {0ull, 0ull, 0ull, 0ull};

    for (int ec = 0; ec < 8; ec++) {
        int e0 = ec * 32;
        __syncthreads();
#pragma unroll
        for (int q = 0; q < 8; q++) {
            int idx = t + 256 * q;
            int hh = idx >> 9, e = (idx >> 4) & 31, sg = idx & 15;
            float4 v = *(const float4*)(g_P + (size_t)hh * 65536 +
                                        (size_t)(e0 + e) * 256 + c0 + sg * 4);
            *(float4*)&Ps[hh][e][sg * 4] = v;
        }
        __syncthreads();
#pragma unroll
        for (int e = 0; e < 32; e++) {
            unsigned long long a = bcast2(fs[i * 256 + e0 + e]);
            ulonglong2 p0 = *(const ulonglong2*)&Ps[h][e][c8];
            ulonglong2 p1 = *(const ulonglong2*)&Ps[h][e][c8 + 4];
            acc[0] = ffma2(a, p0.x, acc[0]);
            acc[1] = ffma2(a, p0.y, acc[1]);
            acc[2] = ffma2(a, p1.x, acc[2]);
            acc[3] = ffma2(a, p1.y, acc[3]);
        }
    }
    int row = b * 32 + ihx;
#pragma unroll
    for (int q = 0; q < 4; q++) {
        g_t[(size_t)row * 256 + c0 + c8 + 2 * q]     = SCALEF * lo2(acc[q]);
        g_t[(size_t)row * 256 + c0 + c8 + 2 * q + 1] = SCALEF * hi2(acc[q]);
    }
}

// ---------------- fused: dots + inverted softmax + u-accumulation ------------
// grid (32 b, 32 js of 128 j), 128 threads, 36.8KB static smem -> 6 blocks/SM.
// phase1: 8 ih x 4 j per thread; phase2: 8 ih x 8 c per thread.
__global__ void __launch_bounds__(128)
k_fused(int last, float* __restrict__ attn_out) {
    __shared__ __align__(16) float dsm[32 * 132];            // dots/attn [ih][j]
    __shared__ __align__(16) float Bs[16 * 260];             // lnx tile (both phases)
    __shared__ __align__(16) unsigned long long t2[32 * 16]; // a-operand (u64 bcast)

    int b = blockIdx.x, js = blockIdx.y;
    int t = threadIdx.x;
    int ihg = t >> 5;          // warp id: ih group of 8
    int lane = t & 31;         // phase1: 4-j group; phase2: 8-c group
    int j0 = js * 128;

    const float* lnxb = g_lnx + (size_t)b * 4096 * 256;

    unsigned long long acc1[8][2];
#pragma unroll
    for (int ii = 0; ii < 8; ii++) { acc1[ii][0] = 0ull; acc1[ii][1] = 0ull; }

    // ---------- phase 1: dots[ih][j] over c ----------
    for (int cc = 0; cc < 16; cc++) {
        int c0 = cc * 16;
        __syncthreads();
        {   // t2: 32 ih x 16 c
            int ih = t >> 2, cq = (t & 3) * 4;
            float4 v = *(const float4*)(g_t + (size_t)(b * 32 + ih) * 256 + c0 + cq);
            t2[ih * 16 + cq + 0] = bcast2(v.x);
            t2[ih * 16 + cq + 1] = bcast2(v.y);
            t2[ih * 16 + cq + 2] = bcast2(v.z);
            t2[ih * 16 + cq + 3] = bcast2(v.w);
        }
        // Bs as [c][j]: 16 c x 128 j (row stride 132)
#pragma unroll
        for (int q = 0; q < 4; q++) {
            int idx = t + 128 * q;
            int j = idx >> 2, f4 = (idx & 3) * 4;
            float4 v = *(const float4*)(lnxb + (size_t)(j0 + j) * 256 + c0 + f4);
            Bs[(f4 + 0) * 132 + j] = v.x;
            Bs[(f4 + 1) * 132 + j] = v.y;
            Bs[(f4 + 2) * 132 + j] = v.z;
            Bs[(f4 + 3) * 132 + j] = v.w;
        }
        __syncthreads();
#pragma unroll
        for (int c = 0; c < 16; c++) {
            ulonglong2 b0 = *(const ulonglong2*)&Bs[c * 132 + lane * 4];
#pragma unroll
            for (int ii = 0; ii < 8; ii++) {
                unsigned long long a = t2[(ihg * 8 + ii) * 16 + c];
                acc1[ii][0] = ffma2(a, b0.x, acc1[ii][0]);
                acc1[ii][1] = ffma2(a, b0.y, acc1[ii][1]);
            }
        }
    }
    __syncthreads();
#pragma unroll
    for (int ii = 0; ii < 8; ii++)
        *(float4*)&dsm[(ihg * 8 + ii) * 132 + lane * 4] = make_float4(
            lo2(acc1[ii][0]), hi2(acc1[ii][0]), lo2(acc1[ii][1]), hi2(acc1[ii][1]));
    __syncthreads();

    // ---------- softmax over 32 (slot,head) per column j = t ----------
    {
        int j = t;
        float vcol[32], mx = -1e30f;
#pragma unroll
        for (int ih = 0; ih < 32; ih++) { vcol[ih] = dsm[ih * 132 + j]; mx = fmaxf(mx, vcol[ih]); }
        float sum = 0.f;
#pragma unroll
        for (int ih = 0; ih < 32; ih++) { vcol[ih] = __expf(vcol[ih] - mx); sum += vcol[ih]; }
        float inv = 1.f / sum;
#pragma unroll
        for (int ih = 0; ih < 32; ih++) { vcol[ih] *= inv; dsm[ih * 132 + j] = vcol[ih]; }
        if (last) {
#pragma unroll
            for (int i = 0; i < 8; i++)
                attn_out[((size_t)b * 8 + i) * 4096 + j0 + j] =
                    0.25f * (vcol[4 * i] + vcol[4 * i + 1] + vcol[4 * i + 2] + vcol[4 * i + 3]);
        }
    }

    // ---------- phase 2: u[ih][c] += attn[ih][j] * lnx[j][c] ----------
    unsigned long long acc2[8][4];
#pragma unroll
    for (int ii = 0; ii < 8; ii++)
#pragma unroll
        for (int q = 0; q < 4; q++) acc2[ii][q] = 0ull;
    float rs = 0.f;

    for (int jt = 0; jt < 8; jt++) {
        int jb = jt * 16;
        __syncthreads();
        // Bs as [j][c]: 16 j x 256 c (row stride 260)
#pragma unroll
        for (int q = 0; q < 8; q++) {
            int idx = t + 128 * q;
            int r = idx >> 6, f4 = idx & 63;
            *(float4*)&Bs[r * 260 + f4 * 4] =
                *(const float4*)(lnxb + (size_t)(j0 + jb + r) * 256 + f4 * 4);
        }
        {   // A2 pack (reuse t2) + rowsum partial; thread's ih = t>>2
            int ih = t >> 2, jq = (t & 3) * 4;
#pragma unroll
            for (int k = 0; k < 4; k++) {
                float a = dsm[ih * 132 + jb + jq + k];
                rs += a;
                t2[ih * 16 + jq + k] = bcast2(a);
            }
        }
        __syncthreads();
#pragma unroll
        for (int j = 0; j < 16; j++) {
            ulonglong2 b0 = *(const ulonglong2*)&Bs[j * 260 + lane * 8];
            ulonglong2 b1 = *(const ulonglong2*)&Bs[j * 260 + lane * 8 + 4];
#pragma unroll
            for (int ii = 0; ii < 8; ii++) {
                unsigned long long a = t2[(ihg * 8 + ii) * 16 + j];
                acc2[ii][0] = ffma2(a, b0.x, acc2[ii][0]);
                acc2[ii][1] = ffma2(a, b0.y, acc2[ii][1]);
                acc2[ii][2] = ffma2(a, b1.x, acc2[ii][2]);
                acc2[ii][3] = ffma2(a, b1.y, acc2[ii][3]);
            }
        }
    }

    // u partials (slice js; overwrite, no zeroing)
#pragma unroll
    for (int ii = 0; ii < 8; ii++) {
        float* dst = g_upart + ((size_t)(js * 1024) + b * 32 + ihg * 8 + ii) * 256 + lane * 8;
        *(float4*)dst       = make_float4(lo2(acc2[ii][0]), hi2(acc2[ii][0]),
                                          lo2(acc2[ii][1]), hi2(acc2[ii][1]));
        *(float4*)(dst + 4) = make_float4(lo2(acc2[ii][2]), hi2(acc2[ii][2]),
                                          lo2(acc2[ii][3]), hi2(acc2[ii][3]));
    }
    // rowsum: 4 threads share one ih
    rs += __shfl_xor_sync(0xffffffffu, rs, 1);
    rs += __shfl_xor_sync(0xffffffffu, rs, 2);
    if ((t & 3) == 0) atomicAdd(&g_rowsum[b * 32 + (t >> 2)], rs);
}

// ---------------- upd = ((Σu + eps·L)/denom) @ Wv_h^T ----------------
__global__ void __launch_bounds__(256)
k_updproj(const float* __restrict__ Wv) {
    int b = blockIdx.x, dh2 = blockIdx.y;
    int t = threadIdx.x;
    int ihx = t >> 3, dq = (t & 7) * 4;
    int h = ihx & 3, i = ihx >> 2;
    int dbase = dh2 * 32;

    __shared__ __align__(16) float ss[32][256];
    __shared__ float Wvs[4][32][16];
    __shared__ float inv_s[32];

    if (t < 32) inv_s[t] = 1.f / (g_rowsum[b * 32 + t] + 4096.f * EPSF);
    __syncthreads();

#pragma unroll
    for (int q = 0; q < 8; q++) {
        int idx = t + 256 * q;
        int ih = idx >> 6, s4 = idx & 63;
        float4 Lv = *(const float4*)(g_L + b * 256 + s4 * 4);
        float4 a = make_float4(Lv.x * EPSF, Lv.y * EPSF, Lv.z * EPSF, Lv.w * EPSF);
#pragma unroll
        for (int p = 0; p < 32; p++) {
            float4 u = *(const float4*)(g_upart + ((size_t)(p * 1024) + b * 32 + ih) * 256 + s4 * 4);
            a.x += u.x; a.y += u.y; a.z += u.z; a.w += u.w;
        }
        float iv = inv_s[ih];
        a.x *= iv; a.y *= iv; a.z *= iv; a.w *= iv;
        *(float4*)&ss[ih][s4 * 4] = a;
    }

    float acc[4] = {0.f, 0.f, 0.f, 0.f};
    for (int cc = 0; cc < 16; cc++) {
        int c0 = cc * 16;
        __syncthreads();
#pragma unroll
        for (int q = 0; q < 8; q++) {
            int idx = t + 256 * q;
            int hh = idx >> 9, dd = (idx >> 4) & 31, c = idx & 15;
            Wvs[hh][dd][c] = Wv[(size_t)(hh * 64 + dbase + dd) * 256 + c0 + c];
        }
        __syncthreads();
#pragma unroll
        for (int c4 = 0; c4 < 4; c4++) {
            float4 sv = *(const float4*)&ss[ihx][c0 + c4 * 4];
#pragma unroll
            for (int k = 0; k < 4; k++) {
                const float* w = &Wvs[h][dq + k][c4 * 4];
                acc[k] += sv.x * w[0] + sv.y * w[1] + sv.z * w[2] + sv.w * w[3];
            }
        }
    }
#pragma unroll
    for (int k = 0; k < 4; k++)
        g_upd[(size_t)(b * 8 + i) * 256 + h * 64 + dbase + dq + k] = acc[k];
}

// ---------------- combined GRU gate GEMMs ----------------
__global__ void __launch_bounds__(256)
k_gates(const float* __restrict__ W_ih, const float* __restrict__ W_hh,
        const float* __restrict__ b_ih, const float* __restrict__ b_hh) {
    int mode = blockIdx.z;
    const float* A    = mode ? g_fill : g_upd;
    const float* W    = mode ? W_hh : W_ih;
    const float* bias = mode ? b_hh : b_ih;
    float* C = g_gates + mode * 196608;

    __shared__ float As[64][17];
    __shared__ float Bsx[64][17];
    int t = threadIdx.x;
    int row0 = blockIdx.x * 64, col0 = blockIdx.y * 64;
    int tx = t & 15, ty = t >> 4;

    float acc[4][4];
#pragma unroll
    for (int i = 0; i < 4; i++)
#pragma unroll
        for (int j = 0; j < 4; j++) acc[i][j] = 0.f;

    for (int k0 = 0; k0 < 256; k0 += 16) {
        __syncthreads();
        {
            int row = t >> 2, kp = t & 3;
            float4 a4 = *(const float4*)(A + (size_t)(row0 + row) * 256 + k0 + kp * 4);
            As[row][kp * 4 + 0] = a4.x; As[row][kp * 4 + 1] = a4.y;
            As[row][kp * 4 + 2] = a4.z; As[row][kp * 4 + 3] = a4.w;
            float4 b4 = *(const float4*)(W + (size_t)(col0 + row) * 256 + k0 + kp * 4);
            Bsx[row][kp * 4 + 0] = b4.x; Bsx[row][kp * 4 + 1] = b4.y;
            Bsx[row][kp * 4 + 2] = b4.z; Bsx[row][kp * 4 + 3] = b4.w;
        }
        __syncthreads();
#pragma unroll
        for (int kk = 0; kk < 16; kk++) {
            float a[4], bb[4];
#pragma unroll
            for (int i = 0; i < 4; i++) a[i]  = As[ty + 16 * i][kk];
#pragma unroll
            for (int j = 0; j < 4; j++) bb[j] = Bsx[tx + 16 * j][kk];
#pragma unroll
            for (int i = 0; i < 4; i++)
#pragma unroll
                for (int j = 0; j < 4; j++) acc[i][j] += a[i] * bb[j];
        }
    }
#pragma unroll
    for (int i = 0; i < 4; i++)
#pragma unroll
        for (int j = 0; j < 4; j++)
            C[(size_t)(row0 + ty + 16 * i) * 768 + col0 + tx + 16 * j] =
                acc[i][j] + bias[col0 + tx + 16 * j];
}

// ---------------- GRU elementwise ----------------
__global__ void k_gru() {
    int idx = blockIdx.x * blockDim.x + threadIdx.x;
    int r = idx >> 8, c = idx & 255;
    const float* gi = g_gates + (size_t)r * 768;
    const float* gh = g_gates + 196608 + (size_t)r * 768;
    float ir = gi[c], iz = gi[c + 256], in = gi[c + 512];
    float hr = gh[c], hz = gh[c + 256], hn = gh[c + 512];
    float rr = 1.f / (1.f + expf(-(ir + hr)));
    float zz = 1.f / (1.f + expf(-(iz + hz)));
    float nn = tanhf(in + rr * hn);
    float hp = g_fill[idx];
    g_fill[idx] = (1.f - zz) * nn + zz * hp;
}

__global__ void k_copyout(float* __restrict__ dst) {
    int idx = blockIdx.x * blockDim.x + threadIdx.x;
    dst[idx] = g_fill[idx];
}

// ---------------- launcher ----------------
extern "C" void kernel_launch(void* const* d_in, const int* in_sizes, int n_in,
                              void* d_out, int out_size) {
    const float* inputs = (const float*)d_in[0];
    const float* cond   = (const float*)d_in[1];
    const float* Wq     = (const float*)d_in[2];
    const float* Wk     = (const float*)d_in[3];
    const float* Wv     = (const float*)d_in[4];
    const float* W_ih   = (const float*)d_in[5];
    const float* W_hh   = (const float*)d_in[6];
    const float* b_ih   = (const float*)d_in[7];
    const float* b_hh   = (const float*)d_in[8];
    const float* lig    = (const float*)d_in[9];
    const float* lib    = (const float*)d_in[10];
    const float* lfg    = (const float*)d_in[11];
    const float* lfb    = (const float*)d_in[12];
    float* out = (float*)d_out;

    k_rowstats<<<16384, 256>>>(inputs);                         // 1
    k_lnx<<<dim3(32, 32), 256>>>(inputs, lig, lib);             // 2
    k_pcomp<<<dim3(4, 4, 4), 256>>>(Wq, Wk);                    // 3

    for (int it = 0; it < 3; it++) {
        k_lnfill<<<32, 256>>>(lfg, lfb, cond, it == 0);         // 4
        k_tgemm<<<dim3(32, 4), 256>>>();                        // 5
        k_fused<<<dim3(32, 32), 128>>>(it == 2 ? 1 : 0, out + 65536);  // 6
        k_updproj<<<dim3(32, 2), 256>>>(Wv);                    // 7
        k_gates<<<dim3(4, 12, 2), 256>>>(W_ih, W_hh, b_ih, b_hh); // 8
        k_gru<<<256, 256>>>();                                  // 9
    }
    k_copyout<<<64, 1024>>>(out);
}